// round 11
// baseline (speedup 1.0000x reference)
#include <cuda_runtime.h>
#include <cuda_bf16.h>
#include <cstdint>
#include <math.h>

// ---------------------------------------------------------------------------
// Problem constants
// ---------------------------------------------------------------------------
#define B_  8
#define L_  2048
#define C_  512
#define CI_ 256
#define MT_ 16384   // B_*L_

typedef __nv_bfloat16 bf16;

// ---------------------------------------------------------------------------
// Scratch (__device__ globals; allocation-free)
// ---------------------------------------------------------------------------
__device__ bf16   g_inH [(size_t)MT_ * C_];           // inputs hi  [bl][c]
__device__ bf16   g_inL [(size_t)MT_ * C_];           // inputs lo
__device__ bf16   g_xyH [(size_t)MT_ * C_];           // [x_proj | y_proj] hi [bl][512]
__device__ bf16   g_xyL [(size_t)MT_ * C_];
__device__ float  g_scores[(size_t)B_ * L_ * L_];     // f32 logits
__device__ int8_t g_at0[(size_t)B_ * L_ * L_];        // attn digit0 [b][l][m]
__device__ int8_t g_at1[(size_t)B_ * L_ * L_];        // attn digit1
__device__ int8_t g_ot0[(size_t)C_ * MT_];            // o_proj^T digit0 [c][bl]
__device__ int8_t g_ot1[(size_t)C_ * MT_];            // o_proj^T digit1
__device__ bf16   g_wxyH[C_ * C_], g_wxyL[C_ * C_];   // [WxT ; WyT], [n][c]
__device__ bf16   g_wotH[C_ * C_], g_wotL[C_ * C_];   // WoT [d][c]
__device__ float  g_bxy[C_];                          // concat(bx, by)
__device__ float  g_bo [C_];                          // bo copy

// ---------------------------------------------------------------------------
// helpers
// ---------------------------------------------------------------------------
__device__ __forceinline__ uint32_t smem_u32(const void* p) {
    uint32_t a;
    asm("{ .reg .u64 t; cvta.to.shared.u64 t, %1; cvt.u32.u64 %0, t; }"
        : "=r"(a) : "l"(p));
    return a;
}
__device__ __forceinline__ void splitf(float v, bf16& h, bf16& l) {
    h = __float2bfloat16_rn(v);
    l = __float2bfloat16_rn(v - __bfloat162float(h));
}
__device__ __forceinline__ uint32_t pack2(bf16 a, bf16 b) {
    return (uint32_t)__bfloat16_as_ushort(a) |
           ((uint32_t)__bfloat16_as_ushort(b) << 16);
}

#define CP16(dst, src) \
    asm volatile("cp.async.ca.shared.global [%0], [%1], 16;" :: "r"(dst), "l"(src) : "memory")
#define CP_COMMIT() asm volatile("cp.async.commit_group;" ::: "memory")
#define CP_WAIT(n)  asm volatile("cp.async.wait_group %0;" :: "n"(n) : "memory")

#define LDSM_X4(r, a) \
    asm volatile("ldmatrix.sync.aligned.m8n8.x4.shared.b16 {%0,%1,%2,%3}, [%4];" \
        : "=r"((r)[0]), "=r"((r)[1]), "=r"((r)[2]), "=r"((r)[3]) : "r"(a))

__device__ __forceinline__ void mma_bf16(float* d, const uint32_t* a, const uint32_t* b) {
    asm("mma.sync.aligned.m16n8k16.row.col.f32.bf16.bf16.f32 "
        "{%0,%1,%2,%3}, {%4,%5,%6,%7}, {%8,%9}, {%0,%1,%2,%3};"
        : "+f"(d[0]), "+f"(d[1]), "+f"(d[2]), "+f"(d[3])
        : "r"(a[0]), "r"(a[1]), "r"(a[2]), "r"(a[3]), "r"(b[0]), "r"(b[1]));
}
__device__ __forceinline__ void mma_s8(int* d, const uint32_t* a, const uint32_t* b) {
    asm("mma.sync.aligned.m16n8k32.row.col.s32.s8.s8.s32 "
        "{%0,%1,%2,%3}, {%4,%5,%6,%7}, {%8,%9}, {%0,%1,%2,%3};"
        : "+r"(d[0]), "+r"(d[1]), "+r"(d[2]), "+r"(d[3])
        : "r"(a[0]), "r"(a[1]), "r"(a[2]), "r"(a[3]), "r"(b[0]), "r"(b[1]));
}

// fixed-point quantization: radix-128 centered digit split, 14-bit q
__device__ __forceinline__ void qsplit(int q, int& d0, int& d1) {
    d0 = (q + 64) >> 7;          // arithmetic shift (centered)
    d1 = q - (d0 << 7);          // in [-64, 63]
}

// ---------------------------------------------------------------------------
// bf16 GEMM core (R9/R10 winner): 128x128 tile, K-chunk 32, 64B swizzled rows,
// 3-stage ring, single sync/chunk, 8 warps (4M x 2N), warp tile 32x64.
// ---------------------------------------------------------------------------
#define ROWB    64u
#define TILE_B  8192u
#define STAGE_B 32768u
#define NSTAGE  3
#define SMEM_GEMM_TOTAL (NSTAGE * 32768)
#define NTHREADS 256

__device__ __forceinline__ void stage_copy(
    uint32_t stage,
    const bf16* __restrict__ AH, const bf16* __restrict__ AL, int ldA, int m0,
    const bf16* __restrict__ BH, const bf16* __restrict__ BL, int ldB, int n0,
    int k0, int tid)
{
    #pragma unroll
    for (int t = 0; t < 4; ++t) {
        const bf16* base = (t == 0) ? AH : (t == 1) ? AL : (t == 2) ? BH : BL;
        const int ld = (t < 2) ? ldA : ldB;
        const int r0 = (t < 2) ? m0  : n0;
        #pragma unroll
        for (int j = 0; j < 2; ++j) {
            const int seg = tid + NTHREADS * j;
            const int r = seg >> 2, c = seg & 3;
            const int csw = c ^ ((r >> 1) & 3);
            const bf16* src = base + (size_t)(r0 + r) * ld + k0 + c * 8;
            const uint32_t dst = stage + t * TILE_B + r * ROWB + csw * 16u;
            CP16(dst, src);
        }
    }
}

template<int KTOT>
__device__ __forceinline__ void gemm_core(
    float acc[2][8][4],
    const bf16* __restrict__ aH, const bf16* __restrict__ aL, int ldA, int m0,
    const bf16* __restrict__ bH, const bf16* __restrict__ bL, int ldB, int n0,
    uint32_t smem_base, int tid, int wm, int wn, int lane)
{
    constexpr int NC = KTOT / 32;

    const uint32_t key  = (uint32_t)(((lane & 7) >> 1) & 3);
    const uint32_t aRow = (uint32_t)(wm + (lane & 7) + ((lane >> 3) & 1) * 8) * ROWB;
    const uint32_t bRow = (uint32_t)(wn + (lane & 7) + ((lane >> 4) & 1) * 8) * ROWB;
    const uint32_t aCh  = (uint32_t)(lane >> 4);
    const uint32_t bCh  = (uint32_t)((lane >> 3) & 1);

    stage_copy(smem_base, aH, aL, ldA, m0, bH, bL, ldB, n0, 0, tid);
    CP_COMMIT();
    stage_copy(smem_base + STAGE_B, aH, aL, ldA, m0, bH, bL, ldB, n0, 32, tid);
    CP_COMMIT();

    uint32_t stage = smem_base;
    for (int kc = 0; kc < NC; ++kc) {
        if (kc + 1 < NC) { CP_WAIT(1); } else { CP_WAIT(0); }
        __syncthreads();

        #pragma unroll
        for (int ks = 0; ks < 2; ++ks) {
            uint32_t ah[2][4], al[2][4];
            const uint32_t aSw = ((uint32_t)(ks * 2) + aCh) ^ key;
            const uint32_t bSw = ((uint32_t)(ks * 2) + bCh) ^ key;
            #pragma unroll
            for (int mi = 0; mi < 2; ++mi) {
                const uint32_t base = stage + aRow + mi * (16u * ROWB) + aSw * 16u;
                LDSM_X4(ah[mi], base);
                LDSM_X4(al[mi], base + TILE_B);
            }
            #pragma unroll
            for (int h = 0; h < 2; ++h) {
                uint32_t bh2[8], bl2[8];
                #pragma unroll
                for (int q = 0; q < 2; ++q) {
                    const uint32_t base = stage + 2u * TILE_B + bRow
                                        + (uint32_t)(h * 32 + q * 16) * ROWB + bSw * 16u;
                    LDSM_X4(bh2 + q * 4, base);
                    LDSM_X4(bl2 + q * 4, base + TILE_B);
                }
                #pragma unroll
                for (int njl = 0; njl < 4; ++njl) {
                    const int nj = h * 4 + njl;
                    #pragma unroll
                    for (int mi = 0; mi < 2; ++mi)
                        mma_bf16(acc[mi][nj], ah[mi], bh2 + njl * 2);
                }
                #pragma unroll
                for (int njl = 0; njl < 4; ++njl) {
                    const int nj = h * 4 + njl;
                    #pragma unroll
                    for (int mi = 0; mi < 2; ++mi)
                        mma_bf16(acc[mi][nj], ah[mi], bl2 + njl * 2);
                }
                #pragma unroll
                for (int njl = 0; njl < 4; ++njl) {
                    const int nj = h * 4 + njl;
                    #pragma unroll
                    for (int mi = 0; mi < 2; ++mi)
                        mma_bf16(acc[mi][nj], al[mi], bh2 + njl * 2);
                }
            }
        }

        if (kc + 2 < NC) {
            uint32_t wstage = stage + 2 * STAGE_B;
            if (wstage >= smem_base + NSTAGE * STAGE_B) wstage -= NSTAGE * STAGE_B;
            stage_copy(wstage, aH, aL, ldA, m0, bH, bL, ldB, n0, (kc + 2) * 32, tid);
            CP_COMMIT();
        }
        stage += STAGE_B;
        if (stage >= smem_base + NSTAGE * STAGE_B) stage = smem_base;
    }
}

// ---------------------------------------------------------------------------
// Fused projection + o_proj^T (bf16 3-term compute)
// z=0: xy = in @ Wxy^T + bxy[n] -> bf16 HL      grid (4=n, 128=m, .)
// z=1: ot = WoT @ in^T + bo[m]  -> int8 digits  grid (4=m, 128=n, .)
// ---------------------------------------------------------------------------
__global__ __launch_bounds__(NTHREADS, 2) void gemm_projot()
{
    extern __shared__ char smem[];
    const uint32_t smem_base = smem_u32(smem);

    const int tid  = threadIdx.x;
    const int wid  = tid >> 5;
    const int lane = tid & 31;
    const int g    = lane >> 2;
    const int t4   = lane & 3;
    const int wm   = (wid & 3) * 32;
    const int wn   = (wid >> 2) * 64;

    const int zz = blockIdx.z;
    const int m0 = (zz == 0) ? blockIdx.y * 128 : blockIdx.x * 128;
    const int n0 = (zz == 0) ? blockIdx.x * 128 : blockIdx.y * 128;

    const bf16* aH = (zz == 0) ? g_inH  : g_wotH;
    const bf16* aL = (zz == 0) ? g_inL  : g_wotL;
    const bf16* bH = (zz == 0) ? g_wxyH : g_inH;
    const bf16* bL = (zz == 0) ? g_wxyL : g_inL;

    float acc[2][8][4] = {};
    gemm_core<512>(acc, aH, aL, C_, m0, bH, bL, C_, n0, smem_base, tid, wm, wn, lane);

    #pragma unroll
    for (int mi = 0; mi < 2; ++mi) {
        const int r0 = m0 + wm + mi * 16 + g;
        const int r1 = r0 + 8;
        const float bm0 = (zz == 1) ? g_bo[r0] : 0.f;
        const float bm1 = (zz == 1) ? g_bo[r1] : 0.f;
        #pragma unroll
        for (int nj = 0; nj < 8; ++nj) {
            const int col = n0 + wn + nj * 8 + 2 * t4;
            float2 v0 = make_float2(acc[mi][nj][0], acc[mi][nj][1]);
            float2 v1 = make_float2(acc[mi][nj][2], acc[mi][nj][3]);
            if (zz == 0) {
                const float2 bb = *(const float2*)&g_bxy[col];
                v0.x += bb.x; v0.y += bb.y; v1.x += bb.x; v1.y += bb.y;
                bf16 h0, l0, h1, l1;
                splitf(v0.x, h0, l0); splitf(v0.y, h1, l1);
                *(uint32_t*)&g_xyH[(size_t)r0 * C_ + col] = pack2(h0, h1);
                *(uint32_t*)&g_xyL[(size_t)r0 * C_ + col] = pack2(l0, l1);
                splitf(v1.x, h0, l0); splitf(v1.y, h1, l1);
                *(uint32_t*)&g_xyH[(size_t)r1 * C_ + col] = pack2(h0, h1);
                *(uint32_t*)&g_xyL[(size_t)r1 * C_ + col] = pack2(l0, l1);
            } else {
                v0.x += bm0; v0.y += bm0; v1.x += bm1; v1.y += bm1;
                // quantize ot: scale 2032 = 16256/8, clamp |v| < 8
                int q, d0a, d1a, d0b, d1b;
                q = (int)rintf(fminf(fmaxf(v0.x, -7.99f), 7.99f) * 2032.f);
                qsplit(q, d0a, d1a);
                q = (int)rintf(fminf(fmaxf(v0.y, -7.99f), 7.99f) * 2032.f);
                qsplit(q, d0b, d1b);
                *(unsigned short*)&g_ot0[(size_t)r0 * MT_ + col] =
                    (unsigned short)((d0a & 255) | ((d0b & 255) << 8));
                *(unsigned short*)&g_ot1[(size_t)r0 * MT_ + col] =
                    (unsigned short)((d1a & 255) | ((d1b & 255) << 8));
                q = (int)rintf(fminf(fmaxf(v1.x, -7.99f), 7.99f) * 2032.f);
                qsplit(q, d0a, d1a);
                q = (int)rintf(fminf(fmaxf(v1.y, -7.99f), 7.99f) * 2032.f);
                qsplit(q, d0b, d1b);
                *(unsigned short*)&g_ot0[(size_t)r1 * MT_ + col] =
                    (unsigned short)((d0a & 255) | ((d0b & 255) << 8));
                *(unsigned short*)&g_ot1[(size_t)r1 * MT_ + col] =
                    (unsigned short)((d1a & 255) | ((d1b & 255) << 8));
            }
        }
    }
}

// ---------------------------------------------------------------------------
// scores GEMM (bf16 3-term, f32 out)
// ---------------------------------------------------------------------------
__global__ __launch_bounds__(NTHREADS, 2) void gemm_scores()
{
    extern __shared__ char smem[];
    const uint32_t smem_base = smem_u32(smem);

    const int tid  = threadIdx.x;
    const int wid  = tid >> 5;
    const int lane = tid & 31;
    const int g    = lane >> 2;
    const int t4   = lane & 3;
    const int wm   = (wid & 3) * 32;
    const int wn   = (wid >> 2) * 64;

    const int bz = blockIdx.z;
    const int m0 = blockIdx.y * 128;
    const int n0 = blockIdx.x * 128;
    const bf16* aH = g_xyH + (size_t)bz * L_ * C_;
    const bf16* aL = g_xyL + (size_t)bz * L_ * C_;
    const bf16* bH = g_xyH + (size_t)bz * L_ * C_ + CI_;
    const bf16* bL = g_xyL + (size_t)bz * L_ * C_ + CI_;

    float acc[2][8][4] = {};
    gemm_core<256>(acc, aH, aL, C_, m0, bH, bL, C_, n0, smem_base, tid, wm, wn, lane);

    float* Cfb = g_scores + (size_t)bz * L_ * L_;
    #pragma unroll
    for (int mi = 0; mi < 2; ++mi) {
        const int r0 = m0 + wm + mi * 16 + g;
        const int r1 = r0 + 8;
        #pragma unroll
        for (int nj = 0; nj < 8; ++nj) {
            const int col = n0 + wn + nj * 8 + 2 * t4;
            *(float2*)&Cfb[(size_t)r0 * L_ + col] =
                make_float2(acc[mi][nj][0], acc[mi][nj][1]);
            *(float2*)&Cfb[(size_t)r1 * L_ + col] =
                make_float2(acc[mi][nj][2], acc[mi][nj][3]);
        }
    }
}

// ---------------------------------------------------------------------------
// int8 nn_out GEMM: out = inputs + attn @ o_proj
// attn digits (a0,a1), ot digits (b0,b1), radix 128, q = 14-bit, drop a1*b1.
// 128x128 tile, K-chunk 32 (one k32 IMMA step), 4-stage ring, single sync,
// 8 warps (4M x 2N), warp tile 32x64, two s32 accumulator sets.
// ---------------------------------------------------------------------------
#define I_ROWB   64u
#define I_TILE   8192u
#define I_STAGE  32768u
#define I_NSTAGE 4
#define SMEM_I8  (I_NSTAGE * 32768)

__device__ __forceinline__ void stage_copy_i8(
    uint32_t stage,
    const int8_t* __restrict__ A0, const int8_t* __restrict__ A1, int ldA, int m0,
    const int8_t* __restrict__ B0, const int8_t* __restrict__ B1, int ldB, int n0,
    int k0, int tid)
{
    const int r = tid & 127;                 // row 0..127
    const int c = tid >> 7;                  // 16B chunk 0/1
    const int slot = (c + ((r >> 1) & 3)) & 3;
    const uint32_t off = (uint32_t)r * I_ROWB + (uint32_t)slot * 16u;
    const size_t sa = (size_t)(m0 + r) * ldA + k0 + c * 16;
    const size_t sb = (size_t)(n0 + r) * ldB + k0 + c * 16;
    CP16(stage + off,              A0 + sa);
    CP16(stage + I_TILE + off,     A1 + sa);
    CP16(stage + 2 * I_TILE + off, B0 + sb);
    CP16(stage + 3 * I_TILE + off, B1 + sb);
}

__global__ __launch_bounds__(NTHREADS) void gemm_i8_nnout(
    const float* __restrict__ inputs_, float* __restrict__ out_)
{
    extern __shared__ char smem[];
    const uint32_t smem_base = smem_u32(smem);

    const int tid  = threadIdx.x;
    const int wid  = tid >> 5;
    const int lane = tid & 31;
    const int g    = lane >> 2;
    const int t4   = lane & 3;
    const int wm   = (wid & 3) * 32;
    const int wn   = (wid >> 2) * 64;

    const int bz = blockIdx.z;
    const int m0 = blockIdx.y * 128;   // l
    const int n0 = blockIdx.x * 128;   // c

    const int8_t* A0 = g_at0 + (size_t)bz * L_ * L_;
    const int8_t* A1 = g_at1 + (size_t)bz * L_ * L_;
    const int8_t* B0 = g_ot0 + (size_t)bz * L_;      // row stride MT_
    const int8_t* B1 = g_ot1 + (size_t)bz * L_;

    int accM[2][8][4] = {};
    int accD[2][8][4] = {};

    // per-lane ldmatrix offsets (slot invariant under +16-row steps)
    const int aR = wm + (lane & 7) + ((lane >> 3) & 1) * 8;
    const int aC = lane >> 4;
    const uint32_t aOff = (uint32_t)aR * I_ROWB
                        + (uint32_t)((aC + ((aR >> 1) & 3)) & 3) * 16u;
    const int bR = wn + (lane & 7) + ((lane >> 4) & 1) * 8;
    const int bC = (lane >> 3) & 1;
    const uint32_t bOff = (uint32_t)bR * I_ROWB
                        + (uint32_t)((bC + ((bR >> 1) & 3)) & 3) * 16u;

    constexpr int NC = 2048 / 32;   // 64

    stage_copy_i8(smem_base,               A0, A1, L_, m0, B0, B1, MT_, n0, 0,  tid);
    CP_COMMIT();
    stage_copy_i8(smem_base + I_STAGE,     A0, A1, L_, m0, B0, B1, MT_, n0, 32, tid);
    CP_COMMIT();
    stage_copy_i8(smem_base + 2 * I_STAGE, A0, A1, L_, m0, B0, B1, MT_, n0, 64, tid);
    CP_COMMIT();

    uint32_t stage = smem_base;
    for (int kc = 0; kc < NC; ++kc) {
        CP_WAIT(2);
        __syncthreads();

        uint32_t a0f[2][4], a1f[2][4];
        #pragma unroll
        for (int mi = 0; mi < 2; ++mi) {
            LDSM_X4(a0f[mi], stage + aOff + mi * (16u * I_ROWB));
            LDSM_X4(a1f[mi], stage + I_TILE + aOff + mi * (16u * I_ROWB));
        }
        #pragma unroll
        for (int h = 0; h < 2; ++h) {
            uint32_t b0f[8], b1f[8];
            #pragma unroll
            for (int q = 0; q < 2; ++q) {
                const uint32_t base = stage + 2u * I_TILE + bOff
                                    + (uint32_t)(h * 32 + q * 16) * I_ROWB;
                LDSM_X4(b0f + q * 4, base);
                LDSM_X4(b1f + q * 4, base + I_TILE);
            }
            #pragma unroll
            for (int njl = 0; njl < 4; ++njl) {
                const int nj = h * 4 + njl;
                #pragma unroll
                for (int mi = 0; mi < 2; ++mi)
                    mma_s8(accM[mi][nj], a0f[mi], b0f + njl * 2);
            }
            #pragma unroll
            for (int njl = 0; njl < 4; ++njl) {
                const int nj = h * 4 + njl;
                #pragma unroll
                for (int mi = 0; mi < 2; ++mi)
                    mma_s8(accD[mi][nj], a0f[mi], b1f + njl * 2);
            }
            #pragma unroll
            for (int njl = 0; njl < 4; ++njl) {
                const int nj = h * 4 + njl;
                #pragma unroll
                for (int mi = 0; mi < 2; ++mi)
                    mma_s8(accD[mi][nj], a1f[mi], b0f + njl * 2);
            }
        }

        if (kc + 3 < NC) {
            uint32_t w = stage + 3 * I_STAGE;
            if (w >= smem_base + I_NSTAGE * I_STAGE) w -= I_NSTAGE * I_STAGE;
            stage_copy_i8(w, A0, A1, L_, m0, B0, B1, MT_, n0, (kc + 3) * 32, tid);
        }
        CP_COMMIT();   // always commit (possibly empty) to keep group count uniform
        stage += I_STAGE;
        if (stage >= smem_base + I_NSTAGE * I_STAGE) stage = smem_base;
    }

    // epilogue: s_dot = SC*(16384*accM + 128*accD), out = inputs + s_dot
    const float SC = 8.0f / (16256.0f * 16256.0f);
    const float* R = inputs_ + (size_t)bz * L_ * C_;
    float* O = out_ + (size_t)bz * L_ * C_;

    #pragma unroll
    for (int mi = 0; mi < 2; ++mi) {
        const int r0 = m0 + wm + mi * 16 + g;
        const int r1 = r0 + 8;
        #pragma unroll
        for (int nj = 0; nj < 8; ++nj) {
            const int col = n0 + wn + nj * 8 + 2 * t4;
            float2 v0, v1;
            v0.x = SC * (16384.f * (float)accM[mi][nj][0] + 128.f * (float)accD[mi][nj][0]);
            v0.y = SC * (16384.f * (float)accM[mi][nj][1] + 128.f * (float)accD[mi][nj][1]);
            v1.x = SC * (16384.f * (float)accM[mi][nj][2] + 128.f * (float)accD[mi][nj][2]);
            v1.y = SC * (16384.f * (float)accM[mi][nj][3] + 128.f * (float)accD[mi][nj][3]);
            const float2 q0 = *(const float2*)&R[(size_t)r0 * C_ + col];
            const float2 q1 = *(const float2*)&R[(size_t)r1 * C_ + col];
            v0.x += q0.x; v0.y += q0.y; v1.x += q1.x; v1.y += q1.y;
            *(float2*)&O[(size_t)r0 * C_ + col] = v0;
            *(float2*)&O[(size_t)r1 * C_ + col] = v1;
        }
    }
}

// ---------------------------------------------------------------------------
// Decompose inputs f32 -> bf16 hi/lo; first blocks also copy biases
// ---------------------------------------------------------------------------
__global__ __launch_bounds__(256) void decomp_inputs(
    const float* __restrict__ src, int n4,
    const float* __restrict__ bx, const float* __restrict__ by,
    const float* __restrict__ bo)
{
    const int i = blockIdx.x * 256 + threadIdx.x;
    if (i < C_) {
        g_bxy[i] = (i < CI_) ? bx[i] : by[i - CI_];
        g_bo[i]  = bo[i];
    }
    if (i >= n4) return;
    const float4 v = ((const float4*)src)[i];
    bf16 h0, h1, h2, h3, l0, l1, l2, l3;
    splitf(v.x, h0, l0); splitf(v.y, h1, l1);
    splitf(v.z, h2, l2); splitf(v.w, h3, l3);
    ((uint2*)g_inH)[i] = make_uint2(pack2(h0, h1), pack2(h2, h3));
    ((uint2*)g_inL)[i] = make_uint2(pack2(l0, l1), pack2(l2, l3));
}

// ---------------------------------------------------------------------------
// Single prep kernel: z selects Wx / Wy / Wo transpose+decompose
// ---------------------------------------------------------------------------
__global__ void prep_weights(const float* __restrict__ Wx,
                             const float* __restrict__ Wy,
                             const float* __restrict__ Wo)
{
    __shared__ float tbuf[32][33];
    const int zz = blockIdx.z;
    const int Cc = (zz == 2) ? C_ : CI_;
    if (blockIdx.x * 32 >= Cc) return;
    const float* src = (zz == 0) ? Wx : (zz == 1) ? Wy : Wo;
    bf16* H = (zz == 0) ? g_wxyH : (zz == 1) ? g_wxyH + (size_t)CI_ * C_ : g_wotH;
    bf16* L = (zz == 0) ? g_wxyL : (zz == 1) ? g_wxyL + (size_t)CI_ * C_ : g_wotL;

    const int bx = blockIdx.x * 32;
    const int by = blockIdx.y * 32;
    const int x = threadIdx.x, y = threadIdx.y;
    #pragma unroll
    for (int d = 0; d < 32; d += 8)
        tbuf[y + d][x] = src[(size_t)(by + y + d) * Cc + bx + x];
    __syncthreads();
    #pragma unroll
    for (int d = 0; d < 32; d += 8) {
        bf16 h, l;
        splitf(tbuf[x][y + d], h, l);
        H[(size_t)(bx + y + d) * C_ + by + x] = h;
        L[(size_t)(bx + y + d) * C_ + by + x] = l;
    }
}

// ---------------------------------------------------------------------------
// Softmax over batch axis: f32 logits -> int8 digit planes (scale 16256)
// ---------------------------------------------------------------------------
__global__ __launch_bounds__(256) void softmax_batch_i8()
{
    const size_t idx = ((size_t)blockIdx.x * 256 + threadIdx.x) * 4;
    const size_t stride = (size_t)L_ * L_;
    float4 v[B_];
    float4 mx = make_float4(-INFINITY, -INFINITY, -INFINITY, -INFINITY);
    #pragma unroll
    for (int b = 0; b < B_; ++b) {
        v[b] = *(const float4*)&g_scores[b * stride + idx];
        mx.x = fmaxf(mx.x, v[b].x); mx.y = fmaxf(mx.y, v[b].y);
        mx.z = fmaxf(mx.z, v[b].z); mx.w = fmaxf(mx.w, v[b].w);
    }
    float4 s = make_float4(0.f, 0.f, 0.f, 0.f);
    #pragma unroll
    for (int b = 0; b < B_; ++b) {
        v[b].x = __expf(v[b].x - mx.x); s.x += v[b].x;
        v[b].y = __expf(v[b].y - mx.y); s.y += v[b].y;
        v[b].z = __expf(v[b].z - mx.z); s.z += v[b].z;
        v[b].w = __expf(v[b].w - mx.w); s.w += v[b].w;
    }
    const float4 inv = make_float4(16256.f / s.x, 16256.f / s.y,
                                   16256.f / s.z, 16256.f / s.w);
    #pragma unroll
    for (int b = 0; b < B_; ++b) {
        int q, d0, d1;
        uint32_t p0 = 0, p1 = 0;
        q = (int)rintf(v[b].x * inv.x); qsplit(q, d0, d1);
        p0 |= (uint32_t)(d0 & 255);       p1 |= (uint32_t)(d1 & 255);
        q = (int)rintf(v[b].y * inv.y); qsplit(q, d0, d1);
        p0 |= (uint32_t)(d0 & 255) << 8;  p1 |= (uint32_t)(d1 & 255) << 8;
        q = (int)rintf(v[b].z * inv.z); qsplit(q, d0, d1);
        p0 |= (uint32_t)(d0 & 255) << 16; p1 |= (uint32_t)(d1 & 255) << 16;
        q = (int)rintf(v[b].w * inv.w); qsplit(q, d0, d1);
        p0 |= (uint32_t)(d0 & 255) << 24; p1 |= (uint32_t)(d1 & 255) << 24;
        *(uint32_t*)&g_at0[b * stride + idx] = p0;
        *(uint32_t*)&g_at1[b * stride + idx] = p1;
    }
}

// ---------------------------------------------------------------------------
// Launch: inputs, Wx, bx, Wy, by, Wo, bo
// ---------------------------------------------------------------------------
extern "C" void kernel_launch(void* const* d_in, const int* in_sizes, int n_in,
                              void* d_out, int out_size)
{
    const float* inputs = (const float*)d_in[0];
    const float* Wx = (const float*)d_in[1];
    const float* bx = (const float*)d_in[2];
    const float* Wy = (const float*)d_in[3];
    const float* by = (const float*)d_in[4];
    const float* Wo = (const float*)d_in[5];
    const float* bo = (const float*)d_in[6];
    float* out = (float*)d_out;

    cudaFuncSetAttribute((const void*)gemm_projot,
                         cudaFuncAttributeMaxDynamicSharedMemorySize, SMEM_GEMM_TOTAL);
    cudaFuncSetAttribute((const void*)gemm_scores,
                         cudaFuncAttributeMaxDynamicSharedMemorySize, SMEM_GEMM_TOTAL);
    cudaFuncSetAttribute((const void*)gemm_i8_nnout,
                         cudaFuncAttributeMaxDynamicSharedMemorySize, SMEM_I8);

    // 0) decompose inputs (+bias copies), prep weights
    decomp_inputs<<<(MT_ * C_ / 4 + 255) / 256, 256>>>(inputs, MT_ * C_ / 4, bx, by, bo);
    prep_weights<<<dim3(16, 16, 3), dim3(32, 8)>>>(Wx, Wy, Wo);

    // 1) fused projection + o_proj^T
    gemm_projot<<<dim3(4, 128, 2), NTHREADS, SMEM_GEMM_TOTAL>>>();

    // 2) scores[b] = x_proj[b] @ y_proj[b]^T
    gemm_scores<<<dim3(L_ / 128, L_ / 128, B_), NTHREADS, SMEM_GEMM_TOTAL>>>();

    // 3) softmax over batch -> attn int8 digit planes
    softmax_batch_i8<<<(L_ * L_ / 4) / 256, 256>>>();

    // 4) out[b] = inputs[b] + attn[b] @ o_proj[b]  (int8 IMMA)
    gemm_i8_nnout<<<dim3(C_ / 128, L_ / 128, B_), NTHREADS, SMEM_I8>>>(inputs, out);
}

// round 12
// speedup vs baseline: 2.4415x; 2.4415x over previous
#include <cuda_runtime.h>
#include <cuda_fp16.h>
#include <cstdint>
#include <math.h>

// ---------------------------------------------------------------------------
// Problem constants
// ---------------------------------------------------------------------------
#define B_  8
#define L_  2048
#define C_  512
#define CI_ 256
#define MT_ 16384   // B_*L_

typedef __half hf;

// ---------------------------------------------------------------------------
// Scratch (__device__ globals; allocation-free)
// ---------------------------------------------------------------------------
__device__ hf    g_inH [(size_t)MT_ * C_];           // inputs hi  [bl][c]
__device__ hf    g_inL [(size_t)MT_ * C_];           // inputs lo
__device__ hf    g_xyH [(size_t)MT_ * C_];           // [x_proj | y_proj] hi [bl][512]
__device__ hf    g_xyL [(size_t)MT_ * C_];
__device__ hf    g_otH [(size_t)C_ * MT_];           // o_proj^T single plane [c][bl]
__device__ float g_scores[(size_t)B_ * L_ * L_];     // f32 logits
__device__ hf    g_atH [(size_t)B_ * L_ * L_];       // attn hi [b][l][m]
__device__ hf    g_atL [(size_t)B_ * L_ * L_];       // attn lo
__device__ hf    g_wxyH[C_ * C_], g_wxyL[C_ * C_];   // [WxT ; WyT], [n][c]
__device__ hf    g_wotH[C_ * C_], g_wotL[C_ * C_];   // WoT [d][c]
__device__ float g_bxy[C_];                          // concat(bx, by)
__device__ float g_bo [C_];                          // bo copy

// ---------------------------------------------------------------------------
// helpers
// ---------------------------------------------------------------------------
__device__ __forceinline__ uint32_t smem_u32(const void* p) {
    uint32_t a;
    asm("{ .reg .u64 t; cvta.to.shared.u64 t, %1; cvt.u32.u64 %0, t; }"
        : "=r"(a) : "l"(p));
    return a;
}
__device__ __forceinline__ void splitf(float v, hf& h, hf& l) {
    h = __float2half_rn(v);
    l = __float2half_rn(v - __half2float(h));
}
__device__ __forceinline__ uint32_t pack2(hf a, hf b) {
    return (uint32_t)__half_as_ushort(a) |
           ((uint32_t)__half_as_ushort(b) << 16);
}

#define CP16(dst, src) \
    asm volatile("cp.async.ca.shared.global [%0], [%1], 16;" :: "r"(dst), "l"(src) : "memory")
#define CP_COMMIT() asm volatile("cp.async.commit_group;" ::: "memory")
#define CP_WAIT(n)  asm volatile("cp.async.wait_group %0;" :: "n"(n) : "memory")

#define LDSM_X4(r, a) \
    asm volatile("ldmatrix.sync.aligned.m8n8.x4.shared.b16 {%0,%1,%2,%3}, [%4];" \
        : "=r"((r)[0]), "=r"((r)[1]), "=r"((r)[2]), "=r"((r)[3]) : "r"(a))

__device__ __forceinline__ void mma_f16(float* d, const uint32_t* a, const uint32_t* b) {
    asm("mma.sync.aligned.m16n8k16.row.col.f32.f16.f16.f32 "
        "{%0,%1,%2,%3}, {%4,%5,%6,%7}, {%8,%9}, {%0,%1,%2,%3};"
        : "+f"(d[0]), "+f"(d[1]), "+f"(d[2]), "+f"(d[3])
        : "r"(a[0]), "r"(a[1]), "r"(a[2]), "r"(a[3]), "r"(b[0]), "r"(b[1]));
}

// ---------------------------------------------------------------------------
// GEMM core: 128x128 CTA tile, K-chunk 32, 64B swizzled rows, 3-stage ring,
// single sync/chunk, 8 warps (4M x 2N), warp tile 32x64.
// BLO=true : 3-term (Ah,Al,Bh,Bl tiles; acc += ah*bh + ah*bl + al*bh)
// BLO=false: 2-term (Ah,Al,Bh tiles;    acc += ah*bh + al*bh)
// ---------------------------------------------------------------------------
#define ROWB    64u
#define TILE_B  8192u
#define NSTAGE  3
#define NTHREADS 256
#define SMEM_3T (NSTAGE * 4 * 8192)
#define SMEM_2T (NSTAGE * 3 * 8192)

template<bool BLO>
__device__ __forceinline__ void stage_copy(
    uint32_t stage,
    const hf* __restrict__ AH, const hf* __restrict__ AL, int ldA, int m0,
    const hf* __restrict__ BH, const hf* __restrict__ BL, int ldB, int n0,
    int k0, int tid)
{
    constexpr int NT = BLO ? 4 : 3;
    #pragma unroll
    for (int t = 0; t < NT; ++t) {
        const hf* base = (t == 0) ? AH : (t == 1) ? AL : (t == 2) ? BH : BL;
        const int ld = (t < 2) ? ldA : ldB;
        const int r0 = (t < 2) ? m0  : n0;
        #pragma unroll
        for (int j = 0; j < 2; ++j) {
            const int seg = tid + NTHREADS * j;
            const int r = seg >> 2, c = seg & 3;
            const int csw = c ^ ((r >> 1) & 3);
            const hf* src = base + (size_t)(r0 + r) * ld + k0 + c * 8;
            const uint32_t dst = stage + t * TILE_B + r * ROWB + csw * 16u;
            CP16(dst, src);
        }
    }
}

template<int KTOT, bool BLO>
__device__ __forceinline__ void gemm_core(
    float acc[2][8][4],
    const hf* __restrict__ aH, const hf* __restrict__ aL, int ldA, int m0,
    const hf* __restrict__ bH, const hf* __restrict__ bL, int ldB, int n0,
    uint32_t smem_base, int tid, int wm, int wn, int lane)
{
    constexpr int NC = KTOT / 32;
    constexpr uint32_t STG = (BLO ? 4u : 3u) * TILE_B;

    const uint32_t key  = (uint32_t)(((lane & 7) >> 1) & 3);
    const uint32_t aRow = (uint32_t)(wm + (lane & 7) + ((lane >> 3) & 1) * 8) * ROWB;
    const uint32_t bRow = (uint32_t)(wn + (lane & 7) + ((lane >> 4) & 1) * 8) * ROWB;
    const uint32_t aCh  = (uint32_t)(lane >> 4);
    const uint32_t bCh  = (uint32_t)((lane >> 3) & 1);

    stage_copy<BLO>(smem_base, aH, aL, ldA, m0, bH, bL, ldB, n0, 0, tid);
    CP_COMMIT();
    stage_copy<BLO>(smem_base + STG, aH, aL, ldA, m0, bH, bL, ldB, n0, 32, tid);
    CP_COMMIT();

    uint32_t stage = smem_base;
    for (int kc = 0; kc < NC; ++kc) {
        if (kc + 1 < NC) { CP_WAIT(1); } else { CP_WAIT(0); }
        __syncthreads();

        #pragma unroll
        for (int ks = 0; ks < 2; ++ks) {
            uint32_t ah[2][4], al[2][4];
            const uint32_t aSw = ((uint32_t)(ks * 2) + aCh) ^ key;
            const uint32_t bSw = ((uint32_t)(ks * 2) + bCh) ^ key;
            #pragma unroll
            for (int mi = 0; mi < 2; ++mi) {
                const uint32_t base = stage + aRow + mi * (16u * ROWB) + aSw * 16u;
                LDSM_X4(ah[mi], base);
                LDSM_X4(al[mi], base + TILE_B);
            }
            #pragma unroll
            for (int h = 0; h < 2; ++h) {
                uint32_t bh2[8], bl2[8];
                #pragma unroll
                for (int q = 0; q < 2; ++q) {
                    const uint32_t base = stage + 2u * TILE_B + bRow
                                        + (uint32_t)(h * 32 + q * 16) * ROWB + bSw * 16u;
                    LDSM_X4(bh2 + q * 4, base);
                    if (BLO) LDSM_X4(bl2 + q * 4, base + TILE_B);
                }
                #pragma unroll
                for (int njl = 0; njl < 4; ++njl) {
                    const int nj = h * 4 + njl;
                    #pragma unroll
                    for (int mi = 0; mi < 2; ++mi)
                        mma_f16(acc[mi][nj], ah[mi], bh2 + njl * 2);
                }
                if (BLO) {
                    #pragma unroll
                    for (int njl = 0; njl < 4; ++njl) {
                        const int nj = h * 4 + njl;
                        #pragma unroll
                        for (int mi = 0; mi < 2; ++mi)
                            mma_f16(acc[mi][nj], ah[mi], bl2 + njl * 2);
                    }
                }
                #pragma unroll
                for (int njl = 0; njl < 4; ++njl) {
                    const int nj = h * 4 + njl;
                    #pragma unroll
                    for (int mi = 0; mi < 2; ++mi)
                        mma_f16(acc[mi][nj], al[mi], bh2 + njl * 2);
                }
            }
        }

        if (kc + 2 < NC) {
            uint32_t wstage = stage + 2 * STG;
            if (wstage >= smem_base + NSTAGE * STG) wstage -= NSTAGE * STG;
            stage_copy<BLO>(wstage, aH, aL, ldA, m0, bH, bL, ldB, n0, (kc + 2) * 32, tid);
            CP_COMMIT();
        }
        stage += STG;
        if (stage >= smem_base + NSTAGE * STG) stage = smem_base;
    }
}

// ---------------------------------------------------------------------------
// Fused projection + o_proj^T (fp16 3-term compute)
// z=0: xy = in @ Wxy^T + bxy[n] -> fp16 HL      grid (4=n, 128=m, .)
// z=1: ot = WoT @ in^T + bo[m]  -> fp16 single  grid (4=m, 128=n, .)
// ---------------------------------------------------------------------------
__global__ __launch_bounds__(NTHREADS, 2) void gemm_projot()
{
    extern __shared__ char smem[];
    const uint32_t smem_base = smem_u32(smem);

    const int tid  = threadIdx.x;
    const int wid  = tid >> 5;
    const int lane = tid & 31;
    const int g    = lane >> 2;
    const int t4   = lane & 3;
    const int wm   = (wid & 3) * 32;
    const int wn   = (wid >> 2) * 64;

    const int zz = blockIdx.z;
    const int m0 = (zz == 0) ? blockIdx.y * 128 : blockIdx.x * 128;
    const int n0 = (zz == 0) ? blockIdx.x * 128 : blockIdx.y * 128;

    const hf* aH = (zz == 0) ? g_inH  : g_wotH;
    const hf* aL = (zz == 0) ? g_inL  : g_wotL;
    const hf* bH = (zz == 0) ? g_wxyH : g_inH;
    const hf* bL = (zz == 0) ? g_wxyL : g_inL;

    float acc[2][8][4] = {};
    gemm_core<512, true>(acc, aH, aL, C_, m0, bH, bL, C_, n0, smem_base, tid, wm, wn, lane);

    #pragma unroll
    for (int mi = 0; mi < 2; ++mi) {
        const int r0 = m0 + wm + mi * 16 + g;
        const int r1 = r0 + 8;
        const float bm0 = (zz == 1) ? g_bo[r0] : 0.f;
        const float bm1 = (zz == 1) ? g_bo[r1] : 0.f;
        #pragma unroll
        for (int nj = 0; nj < 8; ++nj) {
            const int col = n0 + wn + nj * 8 + 2 * t4;
            float2 v0 = make_float2(acc[mi][nj][0], acc[mi][nj][1]);
            float2 v1 = make_float2(acc[mi][nj][2], acc[mi][nj][3]);
            if (zz == 0) {
                const float2 bb = *(const float2*)&g_bxy[col];
                v0.x += bb.x; v0.y += bb.y; v1.x += bb.x; v1.y += bb.y;
                hf h0, l0, h1, l1;
                splitf(v0.x, h0, l0); splitf(v0.y, h1, l1);
                *(uint32_t*)&g_xyH[(size_t)r0 * C_ + col] = pack2(h0, h1);
                *(uint32_t*)&g_xyL[(size_t)r0 * C_ + col] = pack2(l0, l1);
                splitf(v1.x, h0, l0); splitf(v1.y, h1, l1);
                *(uint32_t*)&g_xyH[(size_t)r1 * C_ + col] = pack2(h0, h1);
                *(uint32_t*)&g_xyL[(size_t)r1 * C_ + col] = pack2(l0, l1);
            } else {
                v0.x += bm0; v0.y += bm0; v1.x += bm1; v1.y += bm1;
                *(uint32_t*)&g_otH[(size_t)r0 * MT_ + col] =
                    pack2(__float2half_rn(v0.x), __float2half_rn(v0.y));
                *(uint32_t*)&g_otH[(size_t)r1 * MT_ + col] =
                    pack2(__float2half_rn(v1.x), __float2half_rn(v1.y));
            }
        }
    }
}

// ---------------------------------------------------------------------------
// scores GEMM (fp16 3-term, f32 out)
// ---------------------------------------------------------------------------
__global__ __launch_bounds__(NTHREADS, 2) void gemm_scores()
{
    extern __shared__ char smem[];
    const uint32_t smem_base = smem_u32(smem);

    const int tid  = threadIdx.x;
    const int wid  = tid >> 5;
    const int lane = tid & 31;
    const int g    = lane >> 2;
    const int t4   = lane & 3;
    const int wm   = (wid & 3) * 32;
    const int wn   = (wid >> 2) * 64;

    const int bz = blockIdx.z;
    const int m0 = blockIdx.y * 128;
    const int n0 = blockIdx.x * 128;
    const hf* aH = g_xyH + (size_t)bz * L_ * C_;
    const hf* aL = g_xyL + (size_t)bz * L_ * C_;
    const hf* bH = aH + CI_;
    const hf* bL = aL + CI_;

    float acc[2][8][4] = {};
    gemm_core<256, true>(acc, aH, aL, C_, m0, bH, bL, C_, n0, smem_base, tid, wm, wn, lane);

    float* Cfb = g_scores + (size_t)bz * L_ * L_;
    #pragma unroll
    for (int mi = 0; mi < 2; ++mi) {
        const int r0 = m0 + wm + mi * 16 + g;
        const int r1 = r0 + 8;
        #pragma unroll
        for (int nj = 0; nj < 8; ++nj) {
            const int col = n0 + wn + nj * 8 + 2 * t4;
            *(float2*)&Cfb[(size_t)r0 * L_ + col] =
                make_float2(acc[mi][nj][0], acc[mi][nj][1]);
            *(float2*)&Cfb[(size_t)r1 * L_ + col] =
                make_float2(acc[mi][nj][2], acc[mi][nj][3]);
        }
    }
}

// ---------------------------------------------------------------------------
// nn_out GEMM (fp16 2-term: attn hi/lo x ot single): out = inputs + attn@o
// ---------------------------------------------------------------------------
__global__ __launch_bounds__(NTHREADS, 2) void gemm_nnout(
    const float* __restrict__ inputs_, float* __restrict__ out_)
{
    extern __shared__ char smem[];
    const uint32_t smem_base = smem_u32(smem);

    const int tid  = threadIdx.x;
    const int wid  = tid >> 5;
    const int lane = tid & 31;
    const int g    = lane >> 2;
    const int t4   = lane & 3;
    const int wm   = (wid & 3) * 32;
    const int wn   = (wid >> 2) * 64;

    const int bz = blockIdx.z;
    const int m0 = blockIdx.y * 128;   // l
    const int n0 = blockIdx.x * 128;   // c
    const hf* aH = g_atH + (size_t)bz * L_ * L_;
    const hf* aL = g_atL + (size_t)bz * L_ * L_;
    const hf* bH = g_otH + (size_t)bz * L_;        // row stride MT_

    float acc[2][8][4] = {};
    gemm_core<2048, false>(acc, aH, aL, L_, m0, bH, nullptr, MT_, n0,
                           smem_base, tid, wm, wn, lane);

    const float* R = inputs_ + (size_t)bz * L_ * C_;
    float* O = out_ + (size_t)bz * L_ * C_;

    #pragma unroll
    for (int mi = 0; mi < 2; ++mi) {
        const int r0 = m0 + wm + mi * 16 + g;
        const int r1 = r0 + 8;
        #pragma unroll
        for (int nj = 0; nj < 8; ++nj) {
            const int col = n0 + wn + nj * 8 + 2 * t4;
            float2 v0 = make_float2(acc[mi][nj][0], acc[mi][nj][1]);
            float2 v1 = make_float2(acc[mi][nj][2], acc[mi][nj][3]);
            const float2 q0 = *(const float2*)&R[(size_t)r0 * C_ + col];
            const float2 q1 = *(const float2*)&R[(size_t)r1 * C_ + col];
            v0.x += q0.x; v0.y += q0.y; v1.x += q1.x; v1.y += q1.y;
            *(float2*)&O[(size_t)r0 * C_ + col] = v0;
            *(float2*)&O[(size_t)r1 * C_ + col] = v1;
        }
    }
}

// ---------------------------------------------------------------------------
// Decompose inputs f32 -> fp16 hi/lo; first blocks also copy biases
// ---------------------------------------------------------------------------
__global__ __launch_bounds__(256) void decomp_inputs(
    const float* __restrict__ src, int n4,
    const float* __restrict__ bx, const float* __restrict__ by,
    const float* __restrict__ bo)
{
    const int i = blockIdx.x * 256 + threadIdx.x;
    if (i < C_) {
        g_bxy[i] = (i < CI_) ? bx[i] : by[i - CI_];
        g_bo[i]  = bo[i];
    }
    if (i >= n4) return;
    const float4 v = ((const float4*)src)[i];
    hf h0, h1, h2, h3, l0, l1, l2, l3;
    splitf(v.x, h0, l0); splitf(v.y, h1, l1);
    splitf(v.z, h2, l2); splitf(v.w, h3, l3);
    ((uint2*)g_inH)[i] = make_uint2(pack2(h0, h1), pack2(h2, h3));
    ((uint2*)g_inL)[i] = make_uint2(pack2(l0, l1), pack2(l2, l3));
}

// ---------------------------------------------------------------------------
// Single prep kernel: z selects Wx / Wy / Wo transpose+decompose (fp16)
// ---------------------------------------------------------------------------
__global__ void prep_weights(const float* __restrict__ Wx,
                             const float* __restrict__ Wy,
                             const float* __restrict__ Wo)
{
    __shared__ float tbuf[32][33];
    const int zz = blockIdx.z;
    const int Cc = (zz == 2) ? C_ : CI_;
    if (blockIdx.x * 32 >= Cc) return;
    const float* src = (zz == 0) ? Wx : (zz == 1) ? Wy : Wo;
    hf* H = (zz == 0) ? g_wxyH : (zz == 1) ? g_wxyH + (size_t)CI_ * C_ : g_wotH;
    hf* L = (zz == 0) ? g_wxyL : (zz == 1) ? g_wxyL + (size_t)CI_ * C_ : g_wotL;

    const int bx = blockIdx.x * 32;
    const int by = blockIdx.y * 32;
    const int x = threadIdx.x, y = threadIdx.y;
    #pragma unroll
    for (int d = 0; d < 32; d += 8)
        tbuf[y + d][x] = src[(size_t)(by + y + d) * Cc + bx + x];
    __syncthreads();
    #pragma unroll
    for (int d = 0; d < 32; d += 8) {
        hf h, l;
        splitf(tbuf[x][y + d], h, l);
        H[(size_t)(bx + y + d) * C_ + by + x] = h;
        L[(size_t)(bx + y + d) * C_ + by + x] = l;
    }
}

// ---------------------------------------------------------------------------
// Softmax over batch axis: f32 logits -> fp16 hi/lo attn planes
// ---------------------------------------------------------------------------
__global__ __launch_bounds__(256) void softmax_batch_HL()
{
    const size_t idx = ((size_t)blockIdx.x * 256 + threadIdx.x) * 4;
    const size_t stride = (size_t)L_ * L_;
    float4 v[B_];
    float4 mx = make_float4(-INFINITY, -INFINITY, -INFINITY, -INFINITY);
    #pragma unroll
    for (int b = 0; b < B_; ++b) {
        v[b] = *(const float4*)&g_scores[b * stride + idx];
        mx.x = fmaxf(mx.x, v[b].x); mx.y = fmaxf(mx.y, v[b].y);
        mx.z = fmaxf(mx.z, v[b].z); mx.w = fmaxf(mx.w, v[b].w);
    }
    float4 s = make_float4(0.f, 0.f, 0.f, 0.f);
    #pragma unroll
    for (int b = 0; b < B_; ++b) {
        v[b].x = __expf(v[b].x - mx.x); s.x += v[b].x;
        v[b].y = __expf(v[b].y - mx.y); s.y += v[b].y;
        v[b].z = __expf(v[b].z - mx.z); s.z += v[b].z;
        v[b].w = __expf(v[b].w - mx.w); s.w += v[b].w;
    }
    const float4 inv = make_float4(1.f / s.x, 1.f / s.y, 1.f / s.z, 1.f / s.w);
    #pragma unroll
    for (int b = 0; b < B_; ++b) {
        hf h0, l0, h1, l1, h2, l2, h3, l3;
        splitf(v[b].x * inv.x, h0, l0);
        splitf(v[b].y * inv.y, h1, l1);
        splitf(v[b].z * inv.z, h2, l2);
        splitf(v[b].w * inv.w, h3, l3);
        *(uint2*)&g_atH[b * stride + idx] = make_uint2(pack2(h0, h1), pack2(h2, h3));
        *(uint2*)&g_atL[b * stride + idx] = make_uint2(pack2(l0, l1), pack2(l2, l3));
    }
}

// ---------------------------------------------------------------------------
// Launch: inputs, Wx, bx, Wy, by, Wo, bo
// ---------------------------------------------------------------------------
extern "C" void kernel_launch(void* const* d_in, const int* in_sizes, int n_in,
                              void* d_out, int out_size)
{
    const float* inputs = (const float*)d_in[0];
    const float* Wx = (const float*)d_in[1];
    const float* bx = (const float*)d_in[2];
    const float* Wy = (const float*)d_in[3];
    const float* by = (const float*)d_in[4];
    const float* Wo = (const float*)d_in[5];
    const float* bo = (const float*)d_in[6];
    float* out = (float*)d_out;

    cudaFuncSetAttribute((const void*)gemm_projot,
                         cudaFuncAttributeMaxDynamicSharedMemorySize, SMEM_3T);
    cudaFuncSetAttribute((const void*)gemm_scores,
                         cudaFuncAttributeMaxDynamicSharedMemorySize, SMEM_3T);
    cudaFuncSetAttribute((const void*)gemm_nnout,
                         cudaFuncAttributeMaxDynamicSharedMemorySize, SMEM_2T);

    // 0) decompose inputs (+bias copies), prep weights
    decomp_inputs<<<(MT_ * C_ / 4 + 255) / 256, 256>>>(inputs, MT_ * C_ / 4, bx, by, bo);
    prep_weights<<<dim3(16, 16, 3), dim3(32, 8)>>>(Wx, Wy, Wo);

    // 1) fused projection + o_proj^T (1024 CTAs, one tail)
    gemm_projot<<<dim3(4, 128, 2), NTHREADS, SMEM_3T>>>();

    // 2) scores[b] = x_proj[b] @ y_proj[b]^T
    gemm_scores<<<dim3(L_ / 128, L_ / 128, B_), NTHREADS, SMEM_3T>>>();

    // 3) softmax over batch -> attn fp16 hi/lo
    softmax_batch_HL<<<(L_ * L_ / 4) / 256, 256>>>();

    // 4) out[b] = inputs[b] + attn[b] @ o_proj[b]  (fp16 2-term)
    gemm_nnout<<<dim3(C_ / 128, L_ / 128, B_), NTHREADS, SMEM_2T>>>(inputs, out);
}

// round 13
// speedup vs baseline: 2.8811x; 1.1801x over previous
#include <cuda_runtime.h>
#include <cuda_fp16.h>
#include <cstdint>
#include <math.h>

// ---------------------------------------------------------------------------
// Problem constants
// ---------------------------------------------------------------------------
#define B_  8
#define L_  2048
#define C_  512
#define CI_ 256
#define MT_ 16384   // B_*L_

typedef __half hf;

// ---------------------------------------------------------------------------
// Scratch (__device__ globals; allocation-free)
// ---------------------------------------------------------------------------
__device__ hf    g_inH [(size_t)MT_ * C_];           // inputs hi  [bl][c]
__device__ hf    g_inL [(size_t)MT_ * C_];           // inputs lo
__device__ hf    g_xyH [(size_t)MT_ * C_];           // [x_proj | y_proj] hi [bl][512]
__device__ hf    g_xyL [(size_t)MT_ * C_];
__device__ hf    g_otH [(size_t)C_ * MT_];           // o_proj^T single plane [c][bl]
__device__ float g_scores[(size_t)B_ * L_ * L_];     // f32 logits
__device__ hf    g_atH [(size_t)B_ * L_ * L_];       // attn single plane [b][l][m]
__device__ hf    g_wxyH[C_ * C_], g_wxyL[C_ * C_];   // [WxT ; WyT], [n][c]
__device__ hf    g_wotH[C_ * C_], g_wotL[C_ * C_];   // WoT [d][c]
__device__ float g_bxy[C_];                          // concat(bx, by)
__device__ float g_bo [C_];                          // bo copy

// ---------------------------------------------------------------------------
// helpers
// ---------------------------------------------------------------------------
__device__ __forceinline__ uint32_t smem_u32(const void* p) {
    uint32_t a;
    asm("{ .reg .u64 t; cvta.to.shared.u64 t, %1; cvt.u32.u64 %0, t; }"
        : "=r"(a) : "l"(p));
    return a;
}
__device__ __forceinline__ void splitf(float v, hf& h, hf& l) {
    h = __float2half_rn(v);
    l = __float2half_rn(v - __half2float(h));
}
__device__ __forceinline__ uint32_t pack2(hf a, hf b) {
    return (uint32_t)__half_as_ushort(a) |
           ((uint32_t)__half_as_ushort(b) << 16);
}

#define CP16(dst, src) \
    asm volatile("cp.async.ca.shared.global [%0], [%1], 16;" :: "r"(dst), "l"(src) : "memory")
#define CP_COMMIT() asm volatile("cp.async.commit_group;" ::: "memory")
#define CP_WAIT(n)  asm volatile("cp.async.wait_group %0;" :: "n"(n) : "memory")

#define LDSM_X4(r, a) \
    asm volatile("ldmatrix.sync.aligned.m8n8.x4.shared.b16 {%0,%1,%2,%3}, [%4];" \
        : "=r"((r)[0]), "=r"((r)[1]), "=r"((r)[2]), "=r"((r)[3]) : "r"(a))

__device__ __forceinline__ void mma_f16(float* d, const uint32_t* a, const uint32_t* b) {
    asm("mma.sync.aligned.m16n8k16.row.col.f32.f16.f16.f32 "
        "{%0,%1,%2,%3}, {%4,%5,%6,%7}, {%8,%9}, {%0,%1,%2,%3};"
        : "+f"(d[0]), "+f"(d[1]), "+f"(d[2]), "+f"(d[3])
        : "r"(a[0]), "r"(a[1]), "r"(a[2]), "r"(a[3]), "r"(b[0]), "r"(b[1]));
}

// ---------------------------------------------------------------------------
// GEMM core: 128x128 CTA tile, K-chunk 32, 64B swizzled rows, 3-stage ring,
// single sync/chunk, 8 warps (4M x 2N), warp tile 32x64.
// NTERM=3: A HL, B HL -> ah*bh + ah*bl + al*bh   (4 tiles/stage)
// NTERM=2: A HL, B H  -> ah*bh + al*bh           (3 tiles/stage)
// NTERM=1: A H,  B H  -> ah*bh                   (2 tiles/stage)
// ---------------------------------------------------------------------------
#define ROWB    64u
#define TILE_B  8192u
#define NSTAGE  3
#define NTHREADS 256
#define SMEM_T(n) (NSTAGE * ((n) + 1) * 8192)

template<int NTERM>
__device__ __forceinline__ void stage_copy(
    uint32_t stage,
    const hf* __restrict__ AH, const hf* __restrict__ AL, int ldA, int m0,
    const hf* __restrict__ BH, const hf* __restrict__ BL, int ldB, int n0,
    int k0, int tid)
{
    constexpr uint32_t B_OFF = (NTERM >= 2 ? 2u : 1u) * TILE_B;
    #pragma unroll
    for (int j = 0; j < 2; ++j) {
        const int seg = tid + NTHREADS * j;
        const int r = seg >> 2, c = seg & 3;
        const int csw = c ^ ((r >> 1) & 3);
        const uint32_t off = (uint32_t)r * ROWB + (uint32_t)csw * 16u;
        const size_t sa = (size_t)(m0 + r) * ldA + k0 + c * 8;
        const size_t sb = (size_t)(n0 + r) * ldB + k0 + c * 8;
        CP16(stage + off, AH + sa);
        if (NTERM >= 2) CP16(stage + TILE_B + off, AL + sa);
        CP16(stage + B_OFF + off, BH + sb);
        if (NTERM == 3) CP16(stage + B_OFF + TILE_B + off, BL + sb);
    }
}

template<int KTOT, int NTERM>
__device__ __forceinline__ void gemm_core(
    float acc[2][8][4],
    const hf* __restrict__ aH, const hf* __restrict__ aL, int ldA, int m0,
    const hf* __restrict__ bH, const hf* __restrict__ bL, int ldB, int n0,
    uint32_t smem_base, int tid, int wm, int wn, int lane)
{
    constexpr int NC = KTOT / 32;
    constexpr uint32_t STG   = (uint32_t)(NTERM + 1) * TILE_B;
    constexpr uint32_t B_OFF = (NTERM >= 2 ? 2u : 1u) * TILE_B;

    const uint32_t key  = (uint32_t)(((lane & 7) >> 1) & 3);
    const uint32_t aRow = (uint32_t)(wm + (lane & 7) + ((lane >> 3) & 1) * 8) * ROWB;
    const uint32_t bRow = (uint32_t)(wn + (lane & 7) + ((lane >> 4) & 1) * 8) * ROWB;
    const uint32_t aCh  = (uint32_t)(lane >> 4);
    const uint32_t bCh  = (uint32_t)((lane >> 3) & 1);

    stage_copy<NTERM>(smem_base, aH, aL, ldA, m0, bH, bL, ldB, n0, 0, tid);
    CP_COMMIT();
    stage_copy<NTERM>(smem_base + STG, aH, aL, ldA, m0, bH, bL, ldB, n0, 32, tid);
    CP_COMMIT();

    uint32_t stage = smem_base;
    for (int kc = 0; kc < NC; ++kc) {
        if (kc + 1 < NC) { CP_WAIT(1); } else { CP_WAIT(0); }
        __syncthreads();

        #pragma unroll
        for (int ks = 0; ks < 2; ++ks) {
            uint32_t ah[2][4], al[2][4];
            const uint32_t aSw = ((uint32_t)(ks * 2) + aCh) ^ key;
            const uint32_t bSw = ((uint32_t)(ks * 2) + bCh) ^ key;
            #pragma unroll
            for (int mi = 0; mi < 2; ++mi) {
                const uint32_t base = stage + aRow + mi * (16u * ROWB) + aSw * 16u;
                LDSM_X4(ah[mi], base);
                if (NTERM >= 2) LDSM_X4(al[mi], base + TILE_B);
            }
            #pragma unroll
            for (int h = 0; h < 2; ++h) {
                uint32_t bh2[8], bl2[8];
                #pragma unroll
                for (int q = 0; q < 2; ++q) {
                    const uint32_t base = stage + B_OFF + bRow
                                        + (uint32_t)(h * 32 + q * 16) * ROWB + bSw * 16u;
                    LDSM_X4(bh2 + q * 4, base);
                    if (NTERM == 3) LDSM_X4(bl2 + q * 4, base + TILE_B);
                }
                #pragma unroll
                for (int njl = 0; njl < 4; ++njl) {
                    const int nj = h * 4 + njl;
                    #pragma unroll
                    for (int mi = 0; mi < 2; ++mi)
                        mma_f16(acc[mi][nj], ah[mi], bh2 + njl * 2);
                }
                if (NTERM == 3) {
                    #pragma unroll
                    for (int njl = 0; njl < 4; ++njl) {
                        const int nj = h * 4 + njl;
                        #pragma unroll
                        for (int mi = 0; mi < 2; ++mi)
                            mma_f16(acc[mi][nj], ah[mi], bl2 + njl * 2);
                    }
                }
                if (NTERM >= 2) {
                    #pragma unroll
                    for (int njl = 0; njl < 4; ++njl) {
                        const int nj = h * 4 + njl;
                        #pragma unroll
                        for (int mi = 0; mi < 2; ++mi)
                            mma_f16(acc[mi][nj], al[mi], bh2 + njl * 2);
                    }
                }
            }
        }

        if (kc + 2 < NC) {
            uint32_t wstage = stage + 2 * STG;
            if (wstage >= smem_base + NSTAGE * STG) wstage -= NSTAGE * STG;
            stage_copy<NTERM>(wstage, aH, aL, ldA, m0, bH, bL, ldB, n0, (kc + 2) * 32, tid);
            CP_COMMIT();
        }
        stage += STG;
        if (stage >= smem_base + NSTAGE * STG) stage = smem_base;
    }
}

// ---------------------------------------------------------------------------
// Fused projection + o_proj^T (fp16 3-term compute)
// z=0: xy = in @ Wxy^T + bxy[n] -> fp16 HL      grid (4=n, 128=m, .)
// z=1: ot = WoT @ in^T + bo[m]  -> fp16 single  grid (4=m, 128=n, .)
// ---------------------------------------------------------------------------
__global__ __launch_bounds__(NTHREADS, 2) void gemm_projot()
{
    extern __shared__ char smem[];
    const uint32_t smem_base = smem_u32(smem);

    const int tid  = threadIdx.x;
    const int wid  = tid >> 5;
    const int lane = tid & 31;
    const int g    = lane >> 2;
    const int t4   = lane & 3;
    const int wm   = (wid & 3) * 32;
    const int wn   = (wid >> 2) * 64;

    const int zz = blockIdx.z;
    const int m0 = (zz == 0) ? blockIdx.y * 128 : blockIdx.x * 128;
    const int n0 = (zz == 0) ? blockIdx.x * 128 : blockIdx.y * 128;

    const hf* aH = (zz == 0) ? g_inH  : g_wotH;
    const hf* aL = (zz == 0) ? g_inL  : g_wotL;
    const hf* bH = (zz == 0) ? g_wxyH : g_inH;
    const hf* bL = (zz == 0) ? g_wxyL : g_inL;

    float acc[2][8][4] = {};
    gemm_core<512, 3>(acc, aH, aL, C_, m0, bH, bL, C_, n0, smem_base, tid, wm, wn, lane);

    #pragma unroll
    for (int mi = 0; mi < 2; ++mi) {
        const int r0 = m0 + wm + mi * 16 + g;
        const int r1 = r0 + 8;
        const float bm0 = (zz == 1) ? g_bo[r0] : 0.f;
        const float bm1 = (zz == 1) ? g_bo[r1] : 0.f;
        #pragma unroll
        for (int nj = 0; nj < 8; ++nj) {
            const int col = n0 + wn + nj * 8 + 2 * t4;
            float2 v0 = make_float2(acc[mi][nj][0], acc[mi][nj][1]);
            float2 v1 = make_float2(acc[mi][nj][2], acc[mi][nj][3]);
            if (zz == 0) {
                const float2 bb = *(const float2*)&g_bxy[col];
                v0.x += bb.x; v0.y += bb.y; v1.x += bb.x; v1.y += bb.y;
                hf h0, l0, h1, l1;
                splitf(v0.x, h0, l0); splitf(v0.y, h1, l1);
                *(uint32_t*)&g_xyH[(size_t)r0 * C_ + col] = pack2(h0, h1);
                *(uint32_t*)&g_xyL[(size_t)r0 * C_ + col] = pack2(l0, l1);
                splitf(v1.x, h0, l0); splitf(v1.y, h1, l1);
                *(uint32_t*)&g_xyH[(size_t)r1 * C_ + col] = pack2(h0, h1);
                *(uint32_t*)&g_xyL[(size_t)r1 * C_ + col] = pack2(l0, l1);
            } else {
                v0.x += bm0; v0.y += bm0; v1.x += bm1; v1.y += bm1;
                *(uint32_t*)&g_otH[(size_t)r0 * MT_ + col] =
                    pack2(__float2half_rn(v0.x), __float2half_rn(v0.y));
                *(uint32_t*)&g_otH[(size_t)r1 * MT_ + col] =
                    pack2(__float2half_rn(v1.x), __float2half_rn(v1.y));
            }
        }
    }
}

// ---------------------------------------------------------------------------
// scores GEMM (fp16 3-term, f32 out)
// ---------------------------------------------------------------------------
__global__ __launch_bounds__(NTHREADS, 2) void gemm_scores()
{
    extern __shared__ char smem[];
    const uint32_t smem_base = smem_u32(smem);

    const int tid  = threadIdx.x;
    const int wid  = tid >> 5;
    const int lane = tid & 31;
    const int g    = lane >> 2;
    const int t4   = lane & 3;
    const int wm   = (wid & 3) * 32;
    const int wn   = (wid >> 2) * 64;

    const int bz = blockIdx.z;
    const int m0 = blockIdx.y * 128;
    const int n0 = blockIdx.x * 128;
    const hf* aH = g_xyH + (size_t)bz * L_ * C_;
    const hf* aL = g_xyL + (size_t)bz * L_ * C_;
    const hf* bH = aH + CI_;
    const hf* bL = aL + CI_;

    float acc[2][8][4] = {};
    gemm_core<256, 3>(acc, aH, aL, C_, m0, bH, bL, C_, n0, smem_base, tid, wm, wn, lane);

    float* Cfb = g_scores + (size_t)bz * L_ * L_;
    #pragma unroll
    for (int mi = 0; mi < 2; ++mi) {
        const int r0 = m0 + wm + mi * 16 + g;
        const int r1 = r0 + 8;
        #pragma unroll
        for (int nj = 0; nj < 8; ++nj) {
            const int col = n0 + wn + nj * 8 + 2 * t4;
            *(float2*)&Cfb[(size_t)r0 * L_ + col] =
                make_float2(acc[mi][nj][0], acc[mi][nj][1]);
            *(float2*)&Cfb[(size_t)r1 * L_ + col] =
                make_float2(acc[mi][nj][2], acc[mi][nj][3]);
        }
    }
}

// ---------------------------------------------------------------------------
// nn_out GEMM (fp16 1-term: attn single x ot single): out = inputs + attn@o
// ---------------------------------------------------------------------------
__global__ __launch_bounds__(NTHREADS, 2) void gemm_nnout(
    const float* __restrict__ inputs_, float* __restrict__ out_)
{
    extern __shared__ char smem[];
    const uint32_t smem_base = smem_u32(smem);

    const int tid  = threadIdx.x;
    const int wid  = tid >> 5;
    const int lane = tid & 31;
    const int g    = lane >> 2;
    const int t4   = lane & 3;
    const int wm   = (wid & 3) * 32;
    const int wn   = (wid >> 2) * 64;

    const int bz = blockIdx.z;
    const int m0 = blockIdx.y * 128;   // l
    const int n0 = blockIdx.x * 128;   // c
    const hf* aH = g_atH + (size_t)bz * L_ * L_;
    const hf* bH = g_otH + (size_t)bz * L_;        // row stride MT_

    float acc[2][8][4] = {};
    gemm_core<2048, 1>(acc, aH, nullptr, L_, m0, bH, nullptr, MT_, n0,
                       smem_base, tid, wm, wn, lane);

    const float* R = inputs_ + (size_t)bz * L_ * C_;
    float* O = out_ + (size_t)bz * L_ * C_;

    #pragma unroll
    for (int mi = 0; mi < 2; ++mi) {
        const int r0 = m0 + wm + mi * 16 + g;
        const int r1 = r0 + 8;
        #pragma unroll
        for (int nj = 0; nj < 8; ++nj) {
            const int col = n0 + wn + nj * 8 + 2 * t4;
            float2 v0 = make_float2(acc[mi][nj][0], acc[mi][nj][1]);
            float2 v1 = make_float2(acc[mi][nj][2], acc[mi][nj][3]);
            const float2 q0 = *(const float2*)&R[(size_t)r0 * C_ + col];
            const float2 q1 = *(const float2*)&R[(size_t)r1 * C_ + col];
            v0.x += q0.x; v0.y += q0.y; v1.x += q1.x; v1.y += q1.y;
            *(float2*)&O[(size_t)r0 * C_ + col] = v0;
            *(float2*)&O[(size_t)r1 * C_ + col] = v1;
        }
    }
}

// ---------------------------------------------------------------------------
// Decompose inputs f32 -> fp16 hi/lo; first blocks also copy biases
// ---------------------------------------------------------------------------
__global__ __launch_bounds__(256) void decomp_inputs(
    const float* __restrict__ src, int n4,
    const float* __restrict__ bx, const float* __restrict__ by,
    const float* __restrict__ bo)
{
    const int i = blockIdx.x * 256 + threadIdx.x;
    if (i < C_) {
        g_bxy[i] = (i < CI_) ? bx[i] : by[i - CI_];
        g_bo[i]  = bo[i];
    }
    if (i >= n4) return;
    const float4 v = ((const float4*)src)[i];
    hf h0, h1, h2, h3, l0, l1, l2, l3;
    splitf(v.x, h0, l0); splitf(v.y, h1, l1);
    splitf(v.z, h2, l2); splitf(v.w, h3, l3);
    ((uint2*)g_inH)[i] = make_uint2(pack2(h0, h1), pack2(h2, h3));
    ((uint2*)g_inL)[i] = make_uint2(pack2(l0, l1), pack2(l2, l3));
}

// ---------------------------------------------------------------------------
// Single prep kernel: z selects Wx / Wy / Wo transpose+decompose (fp16)
// ---------------------------------------------------------------------------
__global__ void prep_weights(const float* __restrict__ Wx,
                             const float* __restrict__ Wy,
                             const float* __restrict__ Wo)
{
    __shared__ float tbuf[32][33];
    const int zz = blockIdx.z;
    const int Cc = (zz == 2) ? C_ : CI_;
    if (blockIdx.x * 32 >= Cc) return;
    const float* src = (zz == 0) ? Wx : (zz == 1) ? Wy : Wo;
    hf* H = (zz == 0) ? g_wxyH : (zz == 1) ? g_wxyH + (size_t)CI_ * C_ : g_wotH;
    hf* L = (zz == 0) ? g_wxyL : (zz == 1) ? g_wxyL + (size_t)CI_ * C_ : g_wotL;

    const int bx = blockIdx.x * 32;
    const int by = blockIdx.y * 32;
    const int x = threadIdx.x, y = threadIdx.y;
    #pragma unroll
    for (int d = 0; d < 32; d += 8)
        tbuf[y + d][x] = src[(size_t)(by + y + d) * Cc + bx + x];
    __syncthreads();
    #pragma unroll
    for (int d = 0; d < 32; d += 8) {
        hf h, l;
        splitf(tbuf[x][y + d], h, l);
        H[(size_t)(bx + y + d) * C_ + by + x] = h;
        L[(size_t)(bx + y + d) * C_ + by + x] = l;
    }
}

// ---------------------------------------------------------------------------
// Softmax over batch axis: f32 logits -> fp16 attn (single plane)
// ---------------------------------------------------------------------------
__global__ __launch_bounds__(256) void softmax_batch()
{
    const size_t idx = ((size_t)blockIdx.x * 256 + threadIdx.x) * 4;
    const size_t stride = (size_t)L_ * L_;
    float4 v[B_];
    float4 mx = make_float4(-INFINITY, -INFINITY, -INFINITY, -INFINITY);
    #pragma unroll
    for (int b = 0; b < B_; ++b) {
        v[b] = *(const float4*)&g_scores[b * stride + idx];
        mx.x = fmaxf(mx.x, v[b].x); mx.y = fmaxf(mx.y, v[b].y);
        mx.z = fmaxf(mx.z, v[b].z); mx.w = fmaxf(mx.w, v[b].w);
    }
    float4 s = make_float4(0.f, 0.f, 0.f, 0.f);
    #pragma unroll
    for (int b = 0; b < B_; ++b) {
        v[b].x = __expf(v[b].x - mx.x); s.x += v[b].x;
        v[b].y = __expf(v[b].y - mx.y); s.y += v[b].y;
        v[b].z = __expf(v[b].z - mx.z); s.z += v[b].z;
        v[b].w = __expf(v[b].w - mx.w); s.w += v[b].w;
    }
    const float4 inv = make_float4(1.f / s.x, 1.f / s.y, 1.f / s.z, 1.f / s.w);
    #pragma unroll
    for (int b = 0; b < B_; ++b) {
        *(uint2*)&g_atH[b * stride + idx] = make_uint2(
            pack2(__float2half_rn(v[b].x * inv.x), __float2half_rn(v[b].y * inv.y)),
            pack2(__float2half_rn(v[b].z * inv.z), __float2half_rn(v[b].w * inv.w)));
    }
}

// ---------------------------------------------------------------------------
// Launch: inputs, Wx, bx, Wy, by, Wo, bo
// ---------------------------------------------------------------------------
extern "C" void kernel_launch(void* const* d_in, const int* in_sizes, int n_in,
                              void* d_out, int out_size)
{
    const float* inputs = (const float*)d_in[0];
    const float* Wx = (const float*)d_in[1];
    const float* bx = (const float*)d_in[2];
    const float* Wy = (const float*)d_in[3];
    const float* by = (const float*)d_in[4];
    const float* Wo = (const float*)d_in[5];
    const float* bo = (const float*)d_in[6];
    float* out = (float*)d_out;

    cudaFuncSetAttribute((const void*)gemm_projot,
                         cudaFuncAttributeMaxDynamicSharedMemorySize, SMEM_T(3));
    cudaFuncSetAttribute((const void*)gemm_scores,
                         cudaFuncAttributeMaxDynamicSharedMemorySize, SMEM_T(3));
    cudaFuncSetAttribute((const void*)gemm_nnout,
                         cudaFuncAttributeMaxDynamicSharedMemorySize, SMEM_T(1));

    // 0) decompose inputs (+bias copies), prep weights
    decomp_inputs<<<(MT_ * C_ / 4 + 255) / 256, 256>>>(inputs, MT_ * C_ / 4, bx, by, bo);
    prep_weights<<<dim3(16, 16, 3), dim3(32, 8)>>>(Wx, Wy, Wo);

    // 1) fused projection + o_proj^T (1024 CTAs, one tail)
    gemm_projot<<<dim3(4, 128, 2), NTHREADS, SMEM_T(3)>>>();

    // 2) scores[b] = x_proj[b] @ y_proj[b]^T
    gemm_scores<<<dim3(L_ / 128, L_ / 128, B_), NTHREADS, SMEM_T(3)>>>();

    // 3) softmax over batch -> attn fp16 (single plane)
    softmax_batch<<<(L_ * L_ / 4) / 256, 256>>>();

    // 4) out[b] = inputs[b] + attn[b] @ o_proj[b]  (fp16 1-term)
    gemm_nnout<<<dim3(C_ / 128, L_ / 128, B_), NTHREADS, SMEM_T(1)>>>(inputs, out);
}

// round 14
// speedup vs baseline: 2.9636x; 1.0286x over previous
#include <cuda_runtime.h>
#include <cuda_fp16.h>
#include <cstdint>
#include <math.h>

// ---------------------------------------------------------------------------
// Problem constants
// ---------------------------------------------------------------------------
#define B_  8
#define L_  2048
#define C_  512
#define CI_ 256
#define MT_ 16384   // B_*L_

typedef __half hf;

// ---------------------------------------------------------------------------
// Scratch (__device__ globals; allocation-free)
// ---------------------------------------------------------------------------
__device__ hf    g_inH [(size_t)MT_ * C_];           // inputs hi  [bl][c]
__device__ hf    g_inL [(size_t)MT_ * C_];           // inputs lo
__device__ hf    g_xyH [(size_t)MT_ * C_];           // [x_proj | y_proj] hi [bl][512]
__device__ hf    g_xyL [(size_t)MT_ * C_];
__device__ hf    g_otH [(size_t)C_ * MT_];           // o_proj^T single plane [c][bl]
__device__ float g_scores[(size_t)B_ * L_ * L_];     // f32 logits
__device__ hf    g_atH [(size_t)B_ * L_ * L_];       // attn single plane [b][l][m]
__device__ hf    g_wxyH[C_ * C_], g_wxyL[C_ * C_];   // [WxT ; WyT], [n][c]
__device__ hf    g_wotH[C_ * C_], g_wotL[C_ * C_];   // WoT [d][c]
__device__ float g_bxy[C_];                          // concat(bx, by)
__device__ float g_bo [C_];                          // bo copy

// ---------------------------------------------------------------------------
// helpers
// ---------------------------------------------------------------------------
__device__ __forceinline__ uint32_t smem_u32(const void* p) {
    uint32_t a;
    asm("{ .reg .u64 t; cvta.to.shared.u64 t, %1; cvt.u32.u64 %0, t; }"
        : "=r"(a) : "l"(p));
    return a;
}
__device__ __forceinline__ void splitf(float v, hf& h, hf& l) {
    h = __float2half_rn(v);
    l = __float2half_rn(v - __half2float(h));
}
__device__ __forceinline__ uint32_t pack2(hf a, hf b) {
    return (uint32_t)__half_as_ushort(a) |
           ((uint32_t)__half_as_ushort(b) << 16);
}

#define CP16(dst, src) \
    asm volatile("cp.async.ca.shared.global [%0], [%1], 16;" :: "r"(dst), "l"(src) : "memory")
#define CP_COMMIT() asm volatile("cp.async.commit_group;" ::: "memory")
#define CP_WAIT(n)  asm volatile("cp.async.wait_group %0;" :: "n"(n) : "memory")

#define LDSM_X4(r, a) \
    asm volatile("ldmatrix.sync.aligned.m8n8.x4.shared.b16 {%0,%1,%2,%3}, [%4];" \
        : "=r"((r)[0]), "=r"((r)[1]), "=r"((r)[2]), "=r"((r)[3]) : "r"(a))

__device__ __forceinline__ void mma_f16(float* d, const uint32_t* a, const uint32_t* b) {
    asm("mma.sync.aligned.m16n8k16.row.col.f32.f16.f16.f32 "
        "{%0,%1,%2,%3}, {%4,%5,%6,%7}, {%8,%9}, {%0,%1,%2,%3};"
        : "+f"(d[0]), "+f"(d[1]), "+f"(d[2]), "+f"(d[3])
        : "r"(a[0]), "r"(a[1]), "r"(a[2]), "r"(a[3]), "r"(b[0]), "r"(b[1]));
}

// ---------------------------------------------------------------------------
// GEMM core: 128x128 CTA tile, K-chunk 32, 64B swizzled rows, 3-stage ring,
// single sync/chunk, 8 warps (4M x 2N), warp tile 32x64.
// NTERM=3: A HL, B HL -> ah*bh + ah*bl + al*bh   (4 tiles/stage)
// NTERM=2: A HL, B H  -> ah*bh + al*bh           (3 tiles/stage)
// NTERM=1: A H,  B H  -> ah*bh                   (2 tiles/stage)
// ---------------------------------------------------------------------------
#define ROWB    64u
#define TILE_B  8192u
#define NSTAGE  3
#define NTHREADS 256
#define SMEM_T(n) (NSTAGE * ((n) + 1) * 8192)

template<int NTERM>
__device__ __forceinline__ void stage_copy(
    uint32_t stage,
    const hf* __restrict__ AH, const hf* __restrict__ AL, int ldA, int m0,
    const hf* __restrict__ BH, const hf* __restrict__ BL, int ldB, int n0,
    int k0, int tid)
{
    constexpr uint32_t B_OFF = (NTERM >= 2 ? 2u : 1u) * TILE_B;
    #pragma unroll
    for (int j = 0; j < 2; ++j) {
        const int seg = tid + NTHREADS * j;
        const int r = seg >> 2, c = seg & 3;
        const int csw = c ^ ((r >> 1) & 3);
        const uint32_t off = (uint32_t)r * ROWB + (uint32_t)csw * 16u;
        const size_t sa = (size_t)(m0 + r) * ldA + k0 + c * 8;
        const size_t sb = (size_t)(n0 + r) * ldB + k0 + c * 8;
        CP16(stage + off, AH + sa);
        if (NTERM >= 2) CP16(stage + TILE_B + off, AL + sa);
        CP16(stage + B_OFF + off, BH + sb);
        if (NTERM == 3) CP16(stage + B_OFF + TILE_B + off, BL + sb);
    }
}

template<int KTOT, int NTERM>
__device__ __forceinline__ void gemm_core(
    float acc[2][8][4],
    const hf* __restrict__ aH, const hf* __restrict__ aL, int ldA, int m0,
    const hf* __restrict__ bH, const hf* __restrict__ bL, int ldB, int n0,
    uint32_t smem_base, int tid, int wm, int wn, int lane)
{
    constexpr int NC = KTOT / 32;
    constexpr uint32_t STG   = (uint32_t)(NTERM + 1) * TILE_B;
    constexpr uint32_t B_OFF = (NTERM >= 2 ? 2u : 1u) * TILE_B;

    const uint32_t key  = (uint32_t)(((lane & 7) >> 1) & 3);
    const uint32_t aRow = (uint32_t)(wm + (lane & 7) + ((lane >> 3) & 1) * 8) * ROWB;
    const uint32_t bRow = (uint32_t)(wn + (lane & 7) + ((lane >> 4) & 1) * 8) * ROWB;
    const uint32_t aCh  = (uint32_t)(lane >> 4);
    const uint32_t bCh  = (uint32_t)((lane >> 3) & 1);

    stage_copy<NTERM>(smem_base, aH, aL, ldA, m0, bH, bL, ldB, n0, 0, tid);
    CP_COMMIT();
    stage_copy<NTERM>(smem_base + STG, aH, aL, ldA, m0, bH, bL, ldB, n0, 32, tid);
    CP_COMMIT();

    uint32_t stage = smem_base;
    for (int kc = 0; kc < NC; ++kc) {
        if (kc + 1 < NC) { CP_WAIT(1); } else { CP_WAIT(0); }
        __syncthreads();

        #pragma unroll
        for (int ks = 0; ks < 2; ++ks) {
            uint32_t ah[2][4], al[2][4];
            const uint32_t aSw = ((uint32_t)(ks * 2) + aCh) ^ key;
            const uint32_t bSw = ((uint32_t)(ks * 2) + bCh) ^ key;
            #pragma unroll
            for (int mi = 0; mi < 2; ++mi) {
                const uint32_t base = stage + aRow + mi * (16u * ROWB) + aSw * 16u;
                LDSM_X4(ah[mi], base);
                if (NTERM >= 2) LDSM_X4(al[mi], base + TILE_B);
            }
            #pragma unroll
            for (int h = 0; h < 2; ++h) {
                uint32_t bh2[8], bl2[8];
                #pragma unroll
                for (int q = 0; q < 2; ++q) {
                    const uint32_t base = stage + B_OFF + bRow
                                        + (uint32_t)(h * 32 + q * 16) * ROWB + bSw * 16u;
                    LDSM_X4(bh2 + q * 4, base);
                    if (NTERM == 3) LDSM_X4(bl2 + q * 4, base + TILE_B);
                }
                #pragma unroll
                for (int njl = 0; njl < 4; ++njl) {
                    const int nj = h * 4 + njl;
                    #pragma unroll
                    for (int mi = 0; mi < 2; ++mi)
                        mma_f16(acc[mi][nj], ah[mi], bh2 + njl * 2);
                }
                if (NTERM == 3) {
                    #pragma unroll
                    for (int njl = 0; njl < 4; ++njl) {
                        const int nj = h * 4 + njl;
                        #pragma unroll
                        for (int mi = 0; mi < 2; ++mi)
                            mma_f16(acc[mi][nj], ah[mi], bl2 + njl * 2);
                    }
                }
                if (NTERM >= 2) {
                    #pragma unroll
                    for (int njl = 0; njl < 4; ++njl) {
                        const int nj = h * 4 + njl;
                        #pragma unroll
                        for (int mi = 0; mi < 2; ++mi)
                            mma_f16(acc[mi][nj], al[mi], bh2 + njl * 2);
                    }
                }
            }
        }

        if (kc + 2 < NC) {
            uint32_t wstage = stage + 2 * STG;
            if (wstage >= smem_base + NSTAGE * STG) wstage -= NSTAGE * STG;
            stage_copy<NTERM>(wstage, aH, aL, ldA, m0, bH, bL, ldB, n0, (kc + 2) * 32, tid);
            CP_COMMIT();
        }
        stage += STG;
        if (stage >= smem_base + NSTAGE * STG) stage = smem_base;
    }
}

// ---------------------------------------------------------------------------
// Fused projection + o_proj^T
// z=0: xy = in @ Wxy^T + bxy[n] -> fp16 HL      (3-term)   grid (4=n, 128=m, .)
// z=1: ot = WoT @ in^T + bo[m]  -> fp16 single  (2-term)   grid (4=m, 128=n, .)
// ---------------------------------------------------------------------------
__global__ __launch_bounds__(NTHREADS, 2) void gemm_projot()
{
    extern __shared__ char smem[];
    const uint32_t smem_base = smem_u32(smem);

    const int tid  = threadIdx.x;
    const int wid  = tid >> 5;
    const int lane = tid & 31;
    const int g    = lane >> 2;
    const int t4   = lane & 3;
    const int wm   = (wid & 3) * 32;
    const int wn   = (wid >> 2) * 64;

    const int zz = blockIdx.z;
    const int m0 = (zz == 0) ? blockIdx.y * 128 : blockIdx.x * 128;
    const int n0 = (zz == 0) ? blockIdx.x * 128 : blockIdx.y * 128;

    float acc[2][8][4] = {};
    if (zz == 0) {
        gemm_core<512, 3>(acc, g_inH, g_inL, C_, m0, g_wxyH, g_wxyL, C_, n0,
                          smem_base, tid, wm, wn, lane);
    } else {
        // 2-term: (woh + wol) * in_h  (drops w * in_lo, ~2.7e-4 abs on ot)
        gemm_core<512, 2>(acc, g_wotH, g_wotL, C_, m0, g_inH, nullptr, C_, n0,
                          smem_base, tid, wm, wn, lane);
    }

    #pragma unroll
    for (int mi = 0; mi < 2; ++mi) {
        const int r0 = m0 + wm + mi * 16 + g;
        const int r1 = r0 + 8;
        const float bm0 = (zz == 1) ? g_bo[r0] : 0.f;
        const float bm1 = (zz == 1) ? g_bo[r1] : 0.f;
        #pragma unroll
        for (int nj = 0; nj < 8; ++nj) {
            const int col = n0 + wn + nj * 8 + 2 * t4;
            float2 v0 = make_float2(acc[mi][nj][0], acc[mi][nj][1]);
            float2 v1 = make_float2(acc[mi][nj][2], acc[mi][nj][3]);
            if (zz == 0) {
                const float2 bb = *(const float2*)&g_bxy[col];
                v0.x += bb.x; v0.y += bb.y; v1.x += bb.x; v1.y += bb.y;
                hf h0, l0, h1, l1;
                splitf(v0.x, h0, l0); splitf(v0.y, h1, l1);
                *(uint32_t*)&g_xyH[(size_t)r0 * C_ + col] = pack2(h0, h1);
                *(uint32_t*)&g_xyL[(size_t)r0 * C_ + col] = pack2(l0, l1);
                splitf(v1.x, h0, l0); splitf(v1.y, h1, l1);
                *(uint32_t*)&g_xyH[(size_t)r1 * C_ + col] = pack2(h0, h1);
                *(uint32_t*)&g_xyL[(size_t)r1 * C_ + col] = pack2(l0, l1);
            } else {
                v0.x += bm0; v0.y += bm0; v1.x += bm1; v1.y += bm1;
                *(uint32_t*)&g_otH[(size_t)r0 * MT_ + col] =
                    pack2(__float2half_rn(v0.x), __float2half_rn(v0.y));
                *(uint32_t*)&g_otH[(size_t)r1 * MT_ + col] =
                    pack2(__float2half_rn(v1.x), __float2half_rn(v1.y));
            }
        }
    }
}

// ---------------------------------------------------------------------------
// scores GEMM (fp16 3-term, f32 out)
// ---------------------------------------------------------------------------
__global__ __launch_bounds__(NTHREADS, 2) void gemm_scores()
{
    extern __shared__ char smem[];
    const uint32_t smem_base = smem_u32(smem);

    const int tid  = threadIdx.x;
    const int wid  = tid >> 5;
    const int lane = tid & 31;
    const int g    = lane >> 2;
    const int t4   = lane & 3;
    const int wm   = (wid & 3) * 32;
    const int wn   = (wid >> 2) * 64;

    const int bz = blockIdx.z;
    const int m0 = blockIdx.y * 128;
    const int n0 = blockIdx.x * 128;
    const hf* aH = g_xyH + (size_t)bz * L_ * C_;
    const hf* aL = g_xyL + (size_t)bz * L_ * C_;
    const hf* bH = aH + CI_;
    const hf* bL = aL + CI_;

    float acc[2][8][4] = {};
    gemm_core<256, 3>(acc, aH, aL, C_, m0, bH, bL, C_, n0, smem_base, tid, wm, wn, lane);

    float* Cfb = g_scores + (size_t)bz * L_ * L_;
    #pragma unroll
    for (int mi = 0; mi < 2; ++mi) {
        const int r0 = m0 + wm + mi * 16 + g;
        const int r1 = r0 + 8;
        #pragma unroll
        for (int nj = 0; nj < 8; ++nj) {
            const int col = n0 + wn + nj * 8 + 2 * t4;
            *(float2*)&Cfb[(size_t)r0 * L_ + col] =
                make_float2(acc[mi][nj][0], acc[mi][nj][1]);
            *(float2*)&Cfb[(size_t)r1 * L_ + col] =
                make_float2(acc[mi][nj][2], acc[mi][nj][3]);
        }
    }
}

// ---------------------------------------------------------------------------
// nn_out GEMM (fp16 1-term): out = inputs + attn @ o_proj
// ---------------------------------------------------------------------------
__global__ __launch_bounds__(NTHREADS, 2) void gemm_nnout(
    const float* __restrict__ inputs_, float* __restrict__ out_)
{
    extern __shared__ char smem[];
    const uint32_t smem_base = smem_u32(smem);

    const int tid  = threadIdx.x;
    const int wid  = tid >> 5;
    const int lane = tid & 31;
    const int g    = lane >> 2;
    const int t4   = lane & 3;
    const int wm   = (wid & 3) * 32;
    const int wn   = (wid >> 2) * 64;

    const int bz = blockIdx.z;
    const int m0 = blockIdx.y * 128;   // l
    const int n0 = blockIdx.x * 128;   // c
    const hf* aH = g_atH + (size_t)bz * L_ * L_;
    const hf* bH = g_otH + (size_t)bz * L_;        // row stride MT_

    float acc[2][8][4] = {};
    gemm_core<2048, 1>(acc, aH, nullptr, L_, m0, bH, nullptr, MT_, n0,
                       smem_base, tid, wm, wn, lane);

    const float* R = inputs_ + (size_t)bz * L_ * C_;
    float* O = out_ + (size_t)bz * L_ * C_;

    #pragma unroll
    for (int mi = 0; mi < 2; ++mi) {
        const int r0 = m0 + wm + mi * 16 + g;
        const int r1 = r0 + 8;
        #pragma unroll
        for (int nj = 0; nj < 8; ++nj) {
            const int col = n0 + wn + nj * 8 + 2 * t4;
            float2 v0 = make_float2(acc[mi][nj][0], acc[mi][nj][1]);
            float2 v1 = make_float2(acc[mi][nj][2], acc[mi][nj][3]);
            const float2 q0 = *(const float2*)&R[(size_t)r0 * C_ + col];
            const float2 q1 = *(const float2*)&R[(size_t)r1 * C_ + col];
            v0.x += q0.x; v0.y += q0.y; v1.x += q1.x; v1.y += q1.y;
            *(float2*)&O[(size_t)r0 * C_ + col] = v0;
            *(float2*)&O[(size_t)r1 * C_ + col] = v1;
        }
    }
}

// ---------------------------------------------------------------------------
// Decompose inputs f32 -> fp16 hi/lo; first blocks also copy biases
// ---------------------------------------------------------------------------
__global__ __launch_bounds__(256) void decomp_inputs(
    const float* __restrict__ src, int n4,
    const float* __restrict__ bx, const float* __restrict__ by,
    const float* __restrict__ bo)
{
    const int i = blockIdx.x * 256 + threadIdx.x;
    if (i < C_) {
        g_bxy[i] = (i < CI_) ? bx[i] : by[i - CI_];
        g_bo[i]  = bo[i];
    }
    if (i >= n4) return;
    const float4 v = ((const float4*)src)[i];
    hf h0, h1, h2, h3, l0, l1, l2, l3;
    splitf(v.x, h0, l0); splitf(v.y, h1, l1);
    splitf(v.z, h2, l2); splitf(v.w, h3, l3);
    ((uint2*)g_inH)[i] = make_uint2(pack2(h0, h1), pack2(h2, h3));
    ((uint2*)g_inL)[i] = make_uint2(pack2(l0, l1), pack2(l2, l3));
}

// ---------------------------------------------------------------------------
// Single prep kernel: z selects Wx / Wy / Wo transpose+decompose (fp16)
// ---------------------------------------------------------------------------
__global__ void prep_weights(const float* __restrict__ Wx,
                             const float* __restrict__ Wy,
                             const float* __restrict__ Wo)
{
    __shared__ float tbuf[32][33];
    const int zz = blockIdx.z;
    const int Cc = (zz == 2) ? C_ : CI_;
    if (blockIdx.x * 32 >= Cc) return;
    const float* src = (zz == 0) ? Wx : (zz == 1) ? Wy : Wo;
    hf* H = (zz == 0) ? g_wxyH : (zz == 1) ? g_wxyH + (size_t)CI_ * C_ : g_wotH;
    hf* L = (zz == 0) ? g_wxyL : (zz == 1) ? g_wxyL + (size_t)CI_ * C_ : g_wotL;

    const int bx = blockIdx.x * 32;
    const int by = blockIdx.y * 32;
    const int x = threadIdx.x, y = threadIdx.y;
    #pragma unroll
    for (int d = 0; d < 32; d += 8)
        tbuf[y + d][x] = src[(size_t)(by + y + d) * Cc + bx + x];
    __syncthreads();
    #pragma unroll
    for (int d = 0; d < 32; d += 8) {
        hf h, l;
        splitf(tbuf[x][y + d], h, l);
        H[(size_t)(bx + y + d) * C_ + by + x] = h;
        L[(size_t)(bx + y + d) * C_ + by + x] = l;
    }
}

// ---------------------------------------------------------------------------
// Softmax over batch axis: f32 logits -> fp16 attn (8 elements per thread)
// ---------------------------------------------------------------------------
__global__ __launch_bounds__(256) void softmax_batch()
{
    const size_t idx = ((size_t)blockIdx.x * 256 + threadIdx.x) * 8;
    const size_t stride = (size_t)L_ * L_;
    float4 v[B_][2];
    float4 mx0 = make_float4(-INFINITY, -INFINITY, -INFINITY, -INFINITY);
    float4 mx1 = mx0;
    #pragma unroll
    for (int b = 0; b < B_; ++b) {
        v[b][0] = *(const float4*)&g_scores[b * stride + idx];
        v[b][1] = *(const float4*)&g_scores[b * stride + idx + 4];
        mx0.x = fmaxf(mx0.x, v[b][0].x); mx0.y = fmaxf(mx0.y, v[b][0].y);
        mx0.z = fmaxf(mx0.z, v[b][0].z); mx0.w = fmaxf(mx0.w, v[b][0].w);
        mx1.x = fmaxf(mx1.x, v[b][1].x); mx1.y = fmaxf(mx1.y, v[b][1].y);
        mx1.z = fmaxf(mx1.z, v[b][1].z); mx1.w = fmaxf(mx1.w, v[b][1].w);
    }
    float4 s0 = make_float4(0.f, 0.f, 0.f, 0.f), s1 = s0;
    #pragma unroll
    for (int b = 0; b < B_; ++b) {
        v[b][0].x = __expf(v[b][0].x - mx0.x); s0.x += v[b][0].x;
        v[b][0].y = __expf(v[b][0].y - mx0.y); s0.y += v[b][0].y;
        v[b][0].z = __expf(v[b][0].z - mx0.z); s0.z += v[b][0].z;
        v[b][0].w = __expf(v[b][0].w - mx0.w); s0.w += v[b][0].w;
        v[b][1].x = __expf(v[b][1].x - mx1.x); s1.x += v[b][1].x;
        v[b][1].y = __expf(v[b][1].y - mx1.y); s1.y += v[b][1].y;
        v[b][1].z = __expf(v[b][1].z - mx1.z); s1.z += v[b][1].z;
        v[b][1].w = __expf(v[b][1].w - mx1.w); s1.w += v[b][1].w;
    }
    const float4 i0 = make_float4(1.f / s0.x, 1.f / s0.y, 1.f / s0.z, 1.f / s0.w);
    const float4 i1 = make_float4(1.f / s1.x, 1.f / s1.y, 1.f / s1.z, 1.f / s1.w);
    #pragma unroll
    for (int b = 0; b < B_; ++b) {
        uint4 o;
        o.x = pack2(__float2half_rn(v[b][0].x * i0.x), __float2half_rn(v[b][0].y * i0.y));
        o.y = pack2(__float2half_rn(v[b][0].z * i0.z), __float2half_rn(v[b][0].w * i0.w));
        o.z = pack2(__float2half_rn(v[b][1].x * i1.x), __float2half_rn(v[b][1].y * i1.y));
        o.w = pack2(__float2half_rn(v[b][1].z * i1.z), __float2half_rn(v[b][1].w * i1.w));
        *(uint4*)&g_atH[b * stride + idx] = o;
    }
}

// ---------------------------------------------------------------------------
// Launch: inputs, Wx, bx, Wy, by, Wo, bo
// ---------------------------------------------------------------------------
extern "C" void kernel_launch(void* const* d_in, const int* in_sizes, int n_in,
                              void* d_out, int out_size)
{
    const float* inputs = (const float*)d_in[0];
    const float* Wx = (const float*)d_in[1];
    const float* bx = (const float*)d_in[2];
    const float* Wy = (const float*)d_in[3];
    const float* by = (const float*)d_in[4];
    const float* Wo = (const float*)d_in[5];
    const float* bo = (const float*)d_in[6];
    float* out = (float*)d_out;

    cudaFuncSetAttribute((const void*)gemm_projot,
                         cudaFuncAttributeMaxDynamicSharedMemorySize, SMEM_T(3));
    cudaFuncSetAttribute((const void*)gemm_scores,
                         cudaFuncAttributeMaxDynamicSharedMemorySize, SMEM_T(3));
    cudaFuncSetAttribute((const void*)gemm_nnout,
                         cudaFuncAttributeMaxDynamicSharedMemorySize, SMEM_T(1));

    // 0) decompose inputs (+bias copies), prep weights
    decomp_inputs<<<(MT_ * C_ / 4 + 255) / 256, 256>>>(inputs, MT_ * C_ / 4, bx, by, bo);
    prep_weights<<<dim3(16, 16, 3), dim3(32, 8)>>>(Wx, Wy, Wo);

    // 1) fused projection (3-term) + o_proj^T (2-term)
    gemm_projot<<<dim3(4, 128, 2), NTHREADS, SMEM_T(3)>>>();

    // 2) scores[b] = x_proj[b] @ y_proj[b]^T (3-term)
    gemm_scores<<<dim3(L_ / 128, L_ / 128, B_), NTHREADS, SMEM_T(3)>>>();

    // 3) softmax over batch -> attn fp16 (single plane)
    softmax_batch<<<(L_ * L_ / 8) / 256, 256>>>();

    // 4) out[b] = inputs[b] + attn[b] @ o_proj[b]  (fp16 1-term)
    gemm_nnout<<<dim3(C_ / 128, L_ / 128, B_), NTHREADS, SMEM_T(1)>>>(inputs, out);
}